// round 9
// baseline (speedup 1.0000x reference)
#include <cuda_runtime.h>
#include <cuda_fp16.h>
#include <cstdint>

// Problem constants
#define B_    16
#define T_    1024
#define C_    256
#define H_    8
#define D_    32
#define M_TOK (B_ * T_)      // 16384 tokens
#define FF_   (4 * C_)       // 1024
#define QKV_N (3 * C_)       // 768
#define ATT_SCALE 0.0625f
#define LN_EPS 1e-5f

// ---------------------------------------------------------------------------
// Scratch (device globals)
// ---------------------------------------------------------------------------
__device__ __half g_h     [M_TOK * C_];     // ln1 output (fp16)
__device__ float  g_qkv   [M_TOK * QKV_N];  // q|k|v (fp32, attention input)
__device__ __half g_att   [M_TOK * C_];     // attention output (fp16)
__device__ float  g_xmid  [M_TOK * C_];     // x + attn proj (fp32)
__device__ __half g_h2    [M_TOK * C_];     // ln2 output (fp16)
__device__ __half g_ffn   [M_TOK * FF_];    // relu(h2@w1+b1) (fp16)
__device__ __half g_wqkvT [QKV_N * C_];     // [N=768][K=256]
__device__ __half g_wprojT[C_ * C_];
__device__ __half g_w1T   [FF_ * C_];
__device__ __half g_w2T   [C_ * FF_];

// ---------------------------------------------------------------------------
// Small helpers
// ---------------------------------------------------------------------------
__device__ __forceinline__ float tf32_rn(float x) {
    float y;
    asm("cvt.rna.tf32.f32 %0, %1;" : "=f"(y) : "f"(x));
    return y;
}
__device__ __forceinline__ void mma_tf32(float* d,
                                         const uint32_t* a, const uint32_t* b,
                                         const float* c) {
    asm volatile(
        "mma.sync.aligned.m16n8k8.row.col.f32.tf32.tf32.f32 "
        "{%0,%1,%2,%3}, {%4,%5,%6,%7}, {%8,%9}, {%10,%11,%12,%13};"
        : "=f"(d[0]), "=f"(d[1]), "=f"(d[2]), "=f"(d[3])
        : "r"(a[0]), "r"(a[1]), "r"(a[2]), "r"(a[3]),
          "r"(b[0]), "r"(b[1]),
          "f"(c[0]), "f"(c[1]), "f"(c[2]), "f"(c[3]));
}
__device__ __forceinline__ void mma_f16(float* d,
                                        const uint32_t* a, const uint32_t* b,
                                        const float* c) {
    asm volatile(
        "mma.sync.aligned.m16n8k16.row.col.f32.f16.f16.f32 "
        "{%0,%1,%2,%3}, {%4,%5,%6,%7}, {%8,%9}, {%10,%11,%12,%13};"
        : "=f"(d[0]), "=f"(d[1]), "=f"(d[2]), "=f"(d[3])
        : "r"(a[0]), "r"(a[1]), "r"(a[2]), "r"(a[3]),
          "r"(b[0]), "r"(b[1]),
          "f"(c[0]), "f"(c[1]), "f"(c[2]), "f"(c[3]));
}
// swizzled column (uint32 units) for element (row, col) in a [rows][32u32] tile
__device__ __forceinline__ int swz(int row, int k) {
    return k ^ (8 * (row & 3)) ^ (4 * ((row >> 2) & 1));
}
__device__ __forceinline__ void cp_async16(void* sp, const void* gp) {
    uint32_t sa = (uint32_t)__cvta_generic_to_shared(sp);
    asm volatile("cp.async.cg.shared.global [%0], [%1], 16;"
                 :: "r"(sa), "l"(gp) : "memory");
}
#define CP_COMMIT() asm volatile("cp.async.commit_group;" ::: "memory")
#define CP_WAIT1()  asm volatile("cp.async.wait_group 1;" ::: "memory")

// ---------------------------------------------------------------------------
// Weight prep (fp16 outputs), single merged kernel
// ---------------------------------------------------------------------------
#define PREP_TOTAL (QKV_N * C_ + C_ * C_ + C_ * FF_ + FF_ * C_)

__global__ void prep_weights_kernel(
    const float* __restrict__ wq, const float* __restrict__ wk,
    const float* __restrict__ wv, const float* __restrict__ w_proj,
    const float* __restrict__ w1, const float* __restrict__ w2,
    __half* __restrict__ wqkvT, __half* __restrict__ wprojT,
    __half* __restrict__ w1T, __half* __restrict__ w2T) {
    int i = blockIdx.x * blockDim.x + threadIdx.x;
    if (i < QKV_N * C_) {
        int n = i / C_;
        int c = i % C_;
        const float* w = (n < C_) ? wq : ((n < 2 * C_) ? wk : wv);
        int nn = n & (C_ - 1);
        wqkvT[i] = __float2half_rn(w[((size_t)(nn >> 5) * C_ + c) * D_ + (nn & 31)]);
        return;
    }
    i -= QKV_N * C_;
    if (i < C_ * C_) {
        int r = i / C_, c = i % C_;
        wprojT[c * C_ + r] = __float2half_rn(w_proj[i]);
        return;
    }
    i -= C_ * C_;
    if (i < C_ * FF_) {
        int r = i / FF_, c = i % FF_;
        w1T[c * C_ + r] = __float2half_rn(w1[i]);
        return;
    }
    i -= C_ * FF_;
    if (i < FF_ * C_) {
        int r = i / C_, c = i % C_;
        w2T[c * FF_ + r] = __float2half_rn(w2[i]);
    }
}

// ---------------------------------------------------------------------------
// LayerNorm: one warp per 256-float row; OUTPUT fp16 (GEMM A input)
// ---------------------------------------------------------------------------
__global__ __launch_bounds__(256) void layernorm_kernel(
    const float* __restrict__ in, const float* __restrict__ g,
    const float* __restrict__ b, __half* __restrict__ out) {
    int warp = threadIdx.x >> 5;
    int lane = threadIdx.x & 31;
    int row  = blockIdx.x * 8 + warp;

    const float4* rp = (const float4*)(in + (size_t)row * C_);
    float4 v0 = rp[lane];
    float4 v1 = rp[lane + 32];

    float s  = v0.x + v0.y + v0.z + v0.w + v1.x + v1.y + v1.z + v1.w;
    float ss = v0.x * v0.x + v0.y * v0.y + v0.z * v0.z + v0.w * v0.w
             + v1.x * v1.x + v1.y * v1.y + v1.z * v1.z + v1.w * v1.w;
#pragma unroll
    for (int off = 16; off; off >>= 1) {
        s  += __shfl_xor_sync(0xffffffffu, s,  off);
        ss += __shfl_xor_sync(0xffffffffu, ss, off);
    }
    float mean = s * (1.0f / C_);
    float var  = ss * (1.0f / C_) - mean * mean;
    float inv  = rsqrtf(var + LN_EPS);

    const float4* gp = (const float4*)g;
    const float4* bp = (const float4*)b;
    float4 g0 = gp[lane], g1 = gp[lane + 32];
    float4 b0 = bp[lane], b1 = bp[lane + 32];

    half2 h0a = __floats2half2_rn((v0.x - mean) * inv * g0.x + b0.x,
                                  (v0.y - mean) * inv * g0.y + b0.y);
    half2 h0b = __floats2half2_rn((v0.z - mean) * inv * g0.z + b0.z,
                                  (v0.w - mean) * inv * g0.w + b0.w);
    half2 h1a = __floats2half2_rn((v1.x - mean) * inv * g1.x + b1.x,
                                  (v1.y - mean) * inv * g1.y + b1.y);
    half2 h1b = __floats2half2_rn((v1.z - mean) * inv * g1.z + b1.z,
                                  (v1.w - mean) * inv * g1.w + b1.w);

    half2* op = (half2*)(out + (size_t)row * C_);
    op[lane * 2 + 0]  = h0a;
    op[lane * 2 + 1]  = h0b;
    op[lane * 2 + 64] = h1a;
    op[lane * 2 + 65] = h1b;
}

// ---------------------------------------------------------------------------
// fp16 mma.sync GEMM (m16n8k16) with cp.async 2-stage pipeline.
// C[M,N] = A[M,K] @ Bt[N,K]^T (+ epilogue).  A, Bt are fp16; accum fp32.
// CTA tile 128x256, K-chunk 64 halves (128 B/row), 8 warps (2m x 4n),
// warp tile 64x64, XOR swizzle on uint32 columns (same algebra as tf32 ver).
// EPI: 0 = plain fp32 out, 1 = +bias+relu fp16 out, 2 = +bias+residual fp32
// ---------------------------------------------------------------------------
#define GA_U32 (128 * 32)
#define GB_U32 (256 * 32)
#define GEMM_SMEM_BYTES (2 * (GA_U32 + GB_U32) * 4)   // 98304

template <int EPI>
__global__ __launch_bounds__(256, 1) void gemm_mma(
    const __half* __restrict__ A, const __half* __restrict__ Bt,
    void* __restrict__ Cm, const float* __restrict__ bias,
    const float* __restrict__ res, int M, int N, int K) {
    extern __shared__ uint32_t dynsm[];
    uint32_t* const Abuf[2] = { dynsm, dynsm + GA_U32 };
    uint32_t* const Bbuf[2] = { dynsm + 2 * GA_U32, dynsm + 2 * GA_U32 + GB_U32 };

    const int tid  = threadIdx.x;
    const int wid  = tid >> 5;
    const int lane = tid & 31;
    const int wm   = (wid & 1) * 64;
    const int wn   = (wid >> 1) * 64;
    const int gq   = lane >> 2;
    const int tq   = lane & 3;
    const int brow = blockIdx.y * 128;
    const int bcol = blockIdx.x * 256;

    float acc[4][8][4];
#pragma unroll
    for (int i = 0; i < 4; i++)
#pragma unroll
        for (int j = 0; j < 8; j++)
#pragma unroll
            for (int q = 0; q < 4; q++) acc[i][j][q] = 0.0f;

    const __half* Ag = A + (size_t)brow * K;
    const __half* Bg = Bt + (size_t)bcol * K;
    const int KC = K >> 6;                 // 64 halves per chunk

    const int cr = tid >> 3;               // 0..31
    const int cc = (tid & 7) * 4;          // uint32 col 0..28

    auto issue = [&](int kc, int s) {
        const __half* Agn = Ag + kc * 64 + cc * 2;
        const __half* Bgn = Bg + kc * 64 + cc * 2;
        uint32_t* As = Abuf[s];
        uint32_t* Bs = Bbuf[s];
#pragma unroll
        for (int i = 0; i < 4; i++) {
            int r = cr + i * 32;
            cp_async16(&As[r * 32 + swz(r, cc)], Agn + (size_t)r * K);
        }
#pragma unroll
        for (int i = 0; i < 8; i++) {
            int r = cr + i * 32;
            cp_async16(&Bs[r * 32 + swz(r, cc)], Bgn + (size_t)r * K);
        }
    };

    issue(0, 0); CP_COMMIT();
    if (KC > 1) issue(1, 1);
    CP_COMMIT();

    for (int kc = 0; kc < KC; kc++) {
        CP_WAIT1();
        __syncthreads();

        uint32_t* As = Abuf[kc & 1];
        uint32_t* Bs = Bbuf[kc & 1];

#pragma unroll
        for (int ks = 0; ks < 4; ks++) {   // 4 k16-steps per 64-half chunk
            const int colA  = (ks * 8 + tq) ^ (8 * (gq & 3)) ^ (4 * ((gq >> 2) & 1));
            const int colA4 = colA ^ 4;

            uint32_t afr[4][4];
#pragma unroll
            for (int mt = 0; mt < 4; mt++) {
                int m0 = wm + mt * 16;
                afr[mt][0] = As[(m0 + gq    ) * 32 + colA ];
                afr[mt][1] = As[(m0 + gq + 8) * 32 + colA ];
                afr[mt][2] = As[(m0 + gq    ) * 32 + colA4];
                afr[mt][3] = As[(m0 + gq + 8) * 32 + colA4];
            }
            uint32_t bfr[8][2];
#pragma unroll
            for (int nt = 0; nt < 8; nt++) {
                int n0 = wn + nt * 8;
                bfr[nt][0] = Bs[(n0 + gq) * 32 + colA ];
                bfr[nt][1] = Bs[(n0 + gq) * 32 + colA4];
            }
#pragma unroll
            for (int mt = 0; mt < 4; mt++)
#pragma unroll
                for (int nt = 0; nt < 8; nt++)
                    mma_f16(acc[mt][nt], afr[mt], bfr[nt], acc[mt][nt]);
        }
        __syncthreads();
        if (kc + 2 < KC) issue(kc + 2, kc & 1);
        CP_COMMIT();
    }

    // epilogue
#pragma unroll
    for (int mt = 0; mt < 4; mt++) {
        int row0 = brow + wm + mt * 16 + gq;
#pragma unroll
        for (int half_ = 0; half_ < 2; half_++) {
            int row = row0 + half_ * 8;
#pragma unroll
            for (int nt = 0; nt < 8; nt++) {
                int col = bcol + wn + nt * 8 + tq * 2;
                float vx = acc[mt][nt][half_ * 2 + 0];
                float vy = acc[mt][nt][half_ * 2 + 1];
                if (EPI != 0) {
                    vx += bias[col + 0];
                    vy += bias[col + 1];
                }
                if (EPI == 1) {
                    __half* outr = (__half*)Cm + (size_t)row * N;
                    *(half2*)(outr + col) =
                        __floats2half2_rn(fmaxf(vx, 0.0f), fmaxf(vy, 0.0f));
                } else {
                    float* outr = (float*)Cm + (size_t)row * N;
                    if (EPI == 2) {
                        float2 rr = *(const float2*)(res + (size_t)row * N + col);
                        vx += rr.x;
                        vy += rr.y;
                    }
                    *(float2*)(outr + col) = make_float2(vx, vy);
                }
            }
        }
    }
}

// ---------------------------------------------------------------------------
// Tensor-core causal flash attention (tf32 mma.sync), fp16 OUTPUT.
// Conflict-free strides: Q/K=36, V=40, P=68; Ps aliases Qs.
// ---------------------------------------------------------------------------
#define PS_FLOATS (4 * 16 * 68)
#define KS_OFF    PS_FLOATS
#define VS_OFF    (KS_OFF + 2 * 64 * 36)
#define POOL_SZ   (VS_OFF + 2 * 64 * 40)

__global__ __launch_bounds__(128) void attn_tc_kernel(
    const float* __restrict__ qkv, __half* __restrict__ att) {
    __shared__ float pool[POOL_SZ];
    float* const Qs = pool;
    float* const Ps = pool;
    float* const Ks0 = pool + KS_OFF;
    float* const Vs0 = pool + VS_OFF;

    const int bh = blockIdx.x;
    const int b  = bh >> 3;
    const int h  = bh & 7;
    const int qt = blockIdx.y;
    const int tid  = threadIdx.x;
    const int wid  = tid >> 5;
    const int lane = tid & 31;
    const int gq   = lane >> 2;
    const int tq   = lane & 3;
    const size_t tokbase = (size_t)b * T_;
    const int qrow0 = qt * 64;
    const int m0 = wid * 16;

#pragma unroll
    for (int i = 0; i < 4; i++) {
        int e = tid + i * 128;
        int r = e >> 3, c4 = e & 7;
        float4 v = *(const float4*)(qkv + (tokbase + qrow0 + r) * QKV_N + h * D_ + c4 * 4);
        v.x = tf32_rn(v.x * ATT_SCALE);
        v.y = tf32_rn(v.y * ATT_SCALE);
        v.z = tf32_rn(v.z * ATT_SCALE);
        v.w = tf32_rn(v.w * ATT_SCALE);
        *(float4*)&Qs[r * 36 + c4 * 4] = v;
    }

    float4 rk[4], rv[4];
#pragma unroll
    for (int i = 0; i < 4; i++) {
        int e = tid + i * 128;
        int r = e >> 3, c4 = e & 7;
        const float* base = qkv + (tokbase + r) * QKV_N + h * D_ + c4 * 4;
        rk[i] = *(const float4*)(base + C_);
        rv[i] = *(const float4*)(base + 2 * C_);
    }
    __syncthreads();

    uint32_t qf[4][4];
#pragma unroll
    for (int ks = 0; ks < 4; ks++) {
        qf[ks][0] = __float_as_uint(Qs[(m0 + gq    ) * 36 + 8 * ks + tq    ]);
        qf[ks][1] = __float_as_uint(Qs[(m0 + gq + 8) * 36 + 8 * ks + tq    ]);
        qf[ks][2] = __float_as_uint(Qs[(m0 + gq    ) * 36 + 8 * ks + tq + 4]);
        qf[ks][3] = __float_as_uint(Qs[(m0 + gq + 8) * 36 + 8 * ks + tq + 4]);
    }

    const int r0 = qrow0 + m0 + gq;
    const int r1 = r0 + 8;

    float mrow0 = -1e30f, mrow1 = -1e30f;
    float l0 = 0.0f, l1 = 0.0f;
    float o[4][4];
#pragma unroll
    for (int i = 0; i < 4; i++)
#pragma unroll
        for (int j = 0; j < 4; j++) o[i][j] = 0.0f;

    float* const Pw = Ps + wid * 16 * 68;

    for (int s0 = 0; s0 <= qrow0; s0 += 64) {
        const int buf = (s0 >> 6) & 1;
        float* const Ks = Ks0 + buf * 64 * 36;
        float* const Vs = Vs0 + buf * 64 * 40;

#pragma unroll
        for (int i = 0; i < 4; i++) {
            int e = tid + i * 128;
            int r = e >> 3, c4 = e & 7;
            float4 kv, vv;
            kv.x = tf32_rn(rk[i].x); kv.y = tf32_rn(rk[i].y);
            kv.z = tf32_rn(rk[i].z); kv.w = tf32_rn(rk[i].w);
            vv.x = tf32_rn(rv[i].x); vv.y = tf32_rn(rv[i].y);
            vv.z = tf32_rn(rv[i].z); vv.w = tf32_rn(rv[i].w);
            *(float4*)&Ks[r * 36 + c4 * 4] = kv;
            *(float4*)&Vs[r * 40 + c4 * 4] = vv;
        }
        __syncthreads();

        if (s0 + 64 <= qrow0) {
#pragma unroll
            for (int i = 0; i < 4; i++) {
                int e = tid + i * 128;
                int r = e >> 3, c4 = e & 7;
                const float* base = qkv + (tokbase + s0 + 64 + r) * QKV_N + h * D_ + c4 * 4;
                rk[i] = *(const float4*)(base + C_);
                rv[i] = *(const float4*)(base + 2 * C_);
            }
        }

        float S[8][4];
#pragma unroll
        for (int nt = 0; nt < 8; nt++) {
            S[nt][0] = S[nt][1] = S[nt][2] = S[nt][3] = 0.0f;
#pragma unroll
            for (int ks = 0; ks < 4; ks++) {
                uint32_t bfr[2];
                bfr[0] = __float_as_uint(Ks[(nt * 8 + gq) * 36 + 8 * ks + tq    ]);
                bfr[1] = __float_as_uint(Ks[(nt * 8 + gq) * 36 + 8 * ks + tq + 4]);
                mma_tf32(S[nt], qf[ks], bfr, S[nt]);
            }
        }

        if (s0 == qrow0) {
#pragma unroll
            for (int nt = 0; nt < 8; nt++) {
                int col = s0 + nt * 8 + 2 * tq;
                if (col     > r0) S[nt][0] = -1e30f;
                if (col + 1 > r0) S[nt][1] = -1e30f;
                if (col     > r1) S[nt][2] = -1e30f;
                if (col + 1 > r1) S[nt][3] = -1e30f;
            }
        }

        float mx0 = -1e30f, mx1 = -1e30f;
#pragma unroll
        for (int nt = 0; nt < 8; nt++) {
            mx0 = fmaxf(mx0, fmaxf(S[nt][0], S[nt][1]));
            mx1 = fmaxf(mx1, fmaxf(S[nt][2], S[nt][3]));
        }
        mx0 = fmaxf(mx0, __shfl_xor_sync(0xffffffffu, mx0, 1));
        mx0 = fmaxf(mx0, __shfl_xor_sync(0xffffffffu, mx0, 2));
        mx1 = fmaxf(mx1, __shfl_xor_sync(0xffffffffu, mx1, 1));
        mx1 = fmaxf(mx1, __shfl_xor_sync(0xffffffffu, mx1, 2));

        float mn0 = fmaxf(mrow0, mx0);
        float mn1 = fmaxf(mrow1, mx1);
        float a0 = __expf(mrow0 - mn0);
        float a1 = __expf(mrow1 - mn1);
        mrow0 = mn0;
        mrow1 = mn1;

        float sum0 = 0.0f, sum1 = 0.0f;
#pragma unroll
        for (int nt = 0; nt < 8; nt++) {
            S[nt][0] = __expf(S[nt][0] - mn0);
            S[nt][1] = __expf(S[nt][1] - mn0);
            S[nt][2] = __expf(S[nt][2] - mn1);
            S[nt][3] = __expf(S[nt][3] - mn1);
            sum0 += S[nt][0] + S[nt][1];
            sum1 += S[nt][2] + S[nt][3];
        }
        sum0 += __shfl_xor_sync(0xffffffffu, sum0, 1);
        sum0 += __shfl_xor_sync(0xffffffffu, sum0, 2);
        sum1 += __shfl_xor_sync(0xffffffffu, sum1, 1);
        sum1 += __shfl_xor_sync(0xffffffffu, sum1, 2);
        l0 = l0 * a0 + sum0;
        l1 = l1 * a1 + sum1;

#pragma unroll
        for (int d4 = 0; d4 < 4; d4++) {
            o[d4][0] *= a0;
            o[d4][1] *= a0;
            o[d4][2] *= a1;
            o[d4][3] *= a1;
        }

#pragma unroll
        for (int nt = 0; nt < 8; nt++) {
            float2 p0 = make_float2(tf32_rn(S[nt][0]), tf32_rn(S[nt][1]));
            float2 p1 = make_float2(tf32_rn(S[nt][2]), tf32_rn(S[nt][3]));
            *(float2*)&Pw[(gq    ) * 68 + nt * 8 + 2 * tq] = p0;
            *(float2*)&Pw[(gq + 8) * 68 + nt * 8 + 2 * tq] = p1;
        }
        __syncwarp();

#pragma unroll
        for (int ks = 0; ks < 8; ks++) {
            uint32_t pf[4];
            pf[0] = __float_as_uint(Pw[(gq    ) * 68 + 8 * ks + tq    ]);
            pf[1] = __float_as_uint(Pw[(gq + 8) * 68 + 8 * ks + tq    ]);
            pf[2] = __float_as_uint(Pw[(gq    ) * 68 + 8 * ks + tq + 4]);
            pf[3] = __float_as_uint(Pw[(gq + 8) * 68 + 8 * ks + tq + 4]);
#pragma unroll
            for (int d4 = 0; d4 < 4; d4++) {
                uint32_t bfr[2];
                bfr[0] = __float_as_uint(Vs[(8 * ks + tq    ) * 40 + d4 * 8 + gq]);
                bfr[1] = __float_as_uint(Vs[(8 * ks + tq + 4) * 40 + d4 * 8 + gq]);
                mma_tf32(o[d4], pf, bfr, o[d4]);
            }
        }
        __syncwarp();
    }

    // write output as fp16 (feeds proj GEMM A)
    float inv0 = 1.0f / l0;
    float inv1 = 1.0f / l1;
#pragma unroll
    for (int d4 = 0; d4 < 4; d4++) {
        int col = h * D_ + d4 * 8 + 2 * tq;
        *(half2*)(att + (tokbase + r0) * C_ + col) =
            __floats2half2_rn(o[d4][0] * inv0, o[d4][1] * inv0);
        *(half2*)(att + (tokbase + r1) * C_ + col) =
            __floats2half2_rn(o[d4][2] * inv1, o[d4][3] * inv1);
    }
}

// ---------------------------------------------------------------------------
// Launch
// ---------------------------------------------------------------------------
extern "C" void kernel_launch(void* const* d_in, const int* in_sizes, int n_in,
                              void* d_out, int out_size) {
    const float* x      = (const float*)d_in[0];
    const float* wq     = (const float*)d_in[1];
    const float* wk     = (const float*)d_in[2];
    const float* wv     = (const float*)d_in[3];
    const float* w_proj = (const float*)d_in[4];
    const float* b_proj = (const float*)d_in[5];
    const float* w1     = (const float*)d_in[6];
    const float* b1     = (const float*)d_in[7];
    const float* w2     = (const float*)d_in[8];
    const float* b2     = (const float*)d_in[9];
    const float* ln1_g  = (const float*)d_in[10];
    const float* ln1_b  = (const float*)d_in[11];
    const float* ln2_g  = (const float*)d_in[12];
    const float* ln2_b  = (const float*)d_in[13];
    float* out = (float*)d_out;

    __half *p_h, *p_att, *p_h2, *p_ffn;
    __half *p_wqkvT, *p_wprojT, *p_w1T, *p_w2T;
    float *p_qkv, *p_xmid;
    cudaGetSymbolAddress((void**)&p_h,      g_h);
    cudaGetSymbolAddress((void**)&p_qkv,    g_qkv);
    cudaGetSymbolAddress((void**)&p_att,    g_att);
    cudaGetSymbolAddress((void**)&p_xmid,   g_xmid);
    cudaGetSymbolAddress((void**)&p_h2,     g_h2);
    cudaGetSymbolAddress((void**)&p_ffn,    g_ffn);
    cudaGetSymbolAddress((void**)&p_wqkvT,  g_wqkvT);
    cudaGetSymbolAddress((void**)&p_wprojT, g_wprojT);
    cudaGetSymbolAddress((void**)&p_w1T,    g_w1T);
    cudaGetSymbolAddress((void**)&p_w2T,    g_w2T);

    cudaFuncSetAttribute(gemm_mma<0>, cudaFuncAttributeMaxDynamicSharedMemorySize, GEMM_SMEM_BYTES);
    cudaFuncSetAttribute(gemm_mma<1>, cudaFuncAttributeMaxDynamicSharedMemorySize, GEMM_SMEM_BYTES);
    cudaFuncSetAttribute(gemm_mma<2>, cudaFuncAttributeMaxDynamicSharedMemorySize, GEMM_SMEM_BYTES);

    // weight prep (single merged launch, fp16 outputs)
    prep_weights_kernel<<<(PREP_TOTAL + 255) / 256, 256>>>(
        wq, wk, wv, w_proj, w1, w2, p_wqkvT, p_wprojT, p_w1T, p_w2T);

    // 1. h = ln1(x)                       (fp16 output)
    layernorm_kernel<<<M_TOK / 8, 256>>>(x, ln1_g, ln1_b, p_h);

    // 2. qkv = h @ Wqkv                   (fp32 output for attention)
    gemm_mma<0><<<dim3(QKV_N / 256, M_TOK / 128), 256, GEMM_SMEM_BYTES>>>(
        p_h, p_wqkvT, p_qkv, nullptr, nullptr, M_TOK, QKV_N, C_);

    // 3. causal attention                 (fp16 output)
    attn_tc_kernel<<<dim3(B_ * H_, T_ / 64), 128>>>(p_qkv, p_att);

    // 4. xmid = x + att @ w_proj + b_proj (fp32 output)
    gemm_mma<2><<<dim3(C_ / 256, M_TOK / 128), 256, GEMM_SMEM_BYTES>>>(
        p_att, p_wprojT, p_xmid, b_proj, x, M_TOK, C_, C_);

    // 5. h2 = ln2(xmid)                   (fp16 output)
    layernorm_kernel<<<M_TOK / 8, 256>>>(p_xmid, ln2_g, ln2_b, p_h2);

    // 6. ffn = relu(h2 @ w1 + b1)         (fp16 output)
    gemm_mma<1><<<dim3(FF_ / 256, M_TOK / 128), 256, GEMM_SMEM_BYTES>>>(
        p_h2, p_w1T, p_ffn, b1, nullptr, M_TOK, FF_, C_);

    // 7. out = xmid + ffn @ w2 + b2       (fp32 output)
    gemm_mma<2><<<dim3(C_ / 256, M_TOK / 128), 256, GEMM_SMEM_BYTES>>>(
        p_ffn, p_w2T, out, b2, p_xmid, M_TOK, C_, FF_);
}

// round 11
// speedup vs baseline: 1.9052x; 1.9052x over previous
#include <cuda_runtime.h>
#include <cuda_fp16.h>
#include <cstdint>

// Problem constants
#define B_    16
#define T_    1024
#define C_    256
#define H_    8
#define D_    32
#define M_TOK (B_ * T_)      // 16384 tokens
#define FF_   (4 * C_)       // 1024
#define QKV_N (3 * C_)       // 768
#define ATT_SCALE 0.0625f
#define LN_EPS 1e-5f

// ---------------------------------------------------------------------------
// Scratch (device globals)
// ---------------------------------------------------------------------------
__device__ __half g_h     [M_TOK * C_];     // ln1 output (fp16)
__device__ __half g_qkv   [M_TOK * QKV_N];  // q|k|v (fp16; q pre-scaled)
__device__ __half g_att   [M_TOK * C_];     // attention output (fp16)
__device__ float  g_xmid  [M_TOK * C_];     // x + attn proj (fp32)
__device__ __half g_h2    [M_TOK * C_];     // ln2 output (fp16)
__device__ __half g_ffn   [M_TOK * FF_];    // relu(h2@w1+b1) (fp16)
__device__ __half g_wqkvT [QKV_N * C_];     // [N=768][K=256]; q cols scaled
__device__ __half g_wprojT[C_ * C_];
__device__ __half g_w1T   [FF_ * C_];
__device__ __half g_w2T   [C_ * FF_];

// ---------------------------------------------------------------------------
// Small helpers
// ---------------------------------------------------------------------------
__device__ __forceinline__ void mma_f16(float* d,
                                        const uint32_t* a, const uint32_t* b,
                                        const float* c) {
    asm volatile(
        "mma.sync.aligned.m16n8k16.row.col.f32.f16.f16.f32 "
        "{%0,%1,%2,%3}, {%4,%5,%6,%7}, {%8,%9}, {%10,%11,%12,%13};"
        : "=f"(d[0]), "=f"(d[1]), "=f"(d[2]), "=f"(d[3])
        : "r"(a[0]), "r"(a[1]), "r"(a[2]), "r"(a[3]),
          "r"(b[0]), "r"(b[1]),
          "f"(c[0]), "f"(c[1]), "f"(c[2]), "f"(c[3]));
}
__device__ __forceinline__ void mma_f16v(float* d, const uint32_t* a,
                                         uint32_t b0, uint32_t b1,
                                         const float* c) {
    asm volatile(
        "mma.sync.aligned.m16n8k16.row.col.f32.f16.f16.f32 "
        "{%0,%1,%2,%3}, {%4,%5,%6,%7}, {%8,%9}, {%10,%11,%12,%13};"
        : "=f"(d[0]), "=f"(d[1]), "=f"(d[2]), "=f"(d[3])
        : "r"(a[0]), "r"(a[1]), "r"(a[2]), "r"(a[3]),
          "r"(b0), "r"(b1),
          "f"(c[0]), "f"(c[1]), "f"(c[2]), "f"(c[3]));
}
__device__ __forceinline__ void ldsm_x4(uint32_t* r, uint32_t a) {
    asm volatile("ldmatrix.sync.aligned.m8n8.x4.shared.b16 {%0,%1,%2,%3}, [%4];"
                 : "=r"(r[0]), "=r"(r[1]), "=r"(r[2]), "=r"(r[3]) : "r"(a));
}
__device__ __forceinline__ void ldsm_x4_t(uint32_t* r, uint32_t a) {
    asm volatile("ldmatrix.sync.aligned.m8n8.x4.trans.shared.b16 {%0,%1,%2,%3}, [%4];"
                 : "=r"(r[0]), "=r"(r[1]), "=r"(r[2]), "=r"(r[3]) : "r"(a));
}
__device__ __forceinline__ uint32_t f2h2(float x, float y) {
    half2 h = __floats2half2_rn(x, y);
    return *reinterpret_cast<uint32_t*>(&h);
}
// swizzled column (uint32 units) for element (row, col) in a [rows][32u32] tile
__device__ __forceinline__ int swz(int row, int k) {
    return k ^ (8 * (row & 3)) ^ (4 * ((row >> 2) & 1));
}
__device__ __forceinline__ void cp_async16(void* sp, const void* gp) {
    uint32_t sa = (uint32_t)__cvta_generic_to_shared(sp);
    asm volatile("cp.async.cg.shared.global [%0], [%1], 16;"
                 :: "r"(sa), "l"(gp) : "memory");
}
#define CP_COMMIT() asm volatile("cp.async.commit_group;" ::: "memory")
#define CP_WAIT1()  asm volatile("cp.async.wait_group 1;" ::: "memory")

// ---------------------------------------------------------------------------
// Weight prep (fp16 outputs; q columns pre-scaled by ATT_SCALE)
// ---------------------------------------------------------------------------
#define PREP_TOTAL (QKV_N * C_ + C_ * C_ + C_ * FF_ + FF_ * C_)

__global__ void prep_weights_kernel(
    const float* __restrict__ wq, const float* __restrict__ wk,
    const float* __restrict__ wv, const float* __restrict__ w_proj,
    const float* __restrict__ w1, const float* __restrict__ w2,
    __half* __restrict__ wqkvT, __half* __restrict__ wprojT,
    __half* __restrict__ w1T, __half* __restrict__ w2T) {
    int i = blockIdx.x * blockDim.x + threadIdx.x;
    if (i < QKV_N * C_) {
        int n = i / C_;
        int c = i % C_;
        const float* w = (n < C_) ? wq : ((n < 2 * C_) ? wk : wv);
        int nn = n & (C_ - 1);
        float val = w[((size_t)(nn >> 5) * C_ + c) * D_ + (nn & 31)];
        if (n < C_) val *= ATT_SCALE;     // fold attention scale into wq
        wqkvT[i] = __float2half_rn(val);
        return;
    }
    i -= QKV_N * C_;
    if (i < C_ * C_) {
        int r = i / C_, c = i % C_;
        wprojT[c * C_ + r] = __float2half_rn(w_proj[i]);
        return;
    }
    i -= C_ * C_;
    if (i < C_ * FF_) {
        int r = i / FF_, c = i % FF_;
        w1T[c * C_ + r] = __float2half_rn(w1[i]);
        return;
    }
    i -= C_ * FF_;
    if (i < FF_ * C_) {
        int r = i / C_, c = i % C_;
        w2T[c * FF_ + r] = __float2half_rn(w2[i]);
    }
}

// ---------------------------------------------------------------------------
// LayerNorm: one warp per 256-float row; OUTPUT fp16
// ---------------------------------------------------------------------------
__global__ __launch_bounds__(256) void layernorm_kernel(
    const float* __restrict__ in, const float* __restrict__ g,
    const float* __restrict__ b, __half* __restrict__ out) {
    int warp = threadIdx.x >> 5;
    int lane = threadIdx.x & 31;
    int row  = blockIdx.x * 8 + warp;

    const float4* rp = (const float4*)(in + (size_t)row * C_);
    float4 v0 = rp[lane];
    float4 v1 = rp[lane + 32];

    float s  = v0.x + v0.y + v0.z + v0.w + v1.x + v1.y + v1.z + v1.w;
    float ss = v0.x * v0.x + v0.y * v0.y + v0.z * v0.z + v0.w * v0.w
             + v1.x * v1.x + v1.y * v1.y + v1.z * v1.z + v1.w * v1.w;
#pragma unroll
    for (int off = 16; off; off >>= 1) {
        s  += __shfl_xor_sync(0xffffffffu, s,  off);
        ss += __shfl_xor_sync(0xffffffffu, ss, off);
    }
    float mean = s * (1.0f / C_);
    float var  = ss * (1.0f / C_) - mean * mean;
    float inv  = rsqrtf(var + LN_EPS);

    const float4* gp = (const float4*)g;
    const float4* bp = (const float4*)b;
    float4 g0 = gp[lane], g1 = gp[lane + 32];
    float4 b0 = bp[lane], b1 = bp[lane + 32];

    half2 h0a = __floats2half2_rn((v0.x - mean) * inv * g0.x + b0.x,
                                  (v0.y - mean) * inv * g0.y + b0.y);
    half2 h0b = __floats2half2_rn((v0.z - mean) * inv * g0.z + b0.z,
                                  (v0.w - mean) * inv * g0.w + b0.w);
    half2 h1a = __floats2half2_rn((v1.x - mean) * inv * g1.x + b1.x,
                                  (v1.y - mean) * inv * g1.y + b1.y);
    half2 h1b = __floats2half2_rn((v1.z - mean) * inv * g1.z + b1.z,
                                  (v1.w - mean) * inv * g1.w + b1.w);

    half2* op = (half2*)(out + (size_t)row * C_);
    op[lane * 2 + 0]  = h0a;
    op[lane * 2 + 1]  = h0b;
    op[lane * 2 + 64] = h1a;
    op[lane * 2 + 65] = h1b;
}

// ---------------------------------------------------------------------------
// fp16 mma.sync GEMM (m16n8k16) with cp.async 2-stage pipeline.
// EPI: 0 = plain fp32, 1 = +bias+relu fp16, 2 = +bias+residual fp32,
//      3 = plain fp16
// ---------------------------------------------------------------------------
#define GA_U32 (128 * 32)
#define GB_U32 (256 * 32)
#define GEMM_SMEM_BYTES (2 * (GA_U32 + GB_U32) * 4)   // 98304

template <int EPI>
__global__ __launch_bounds__(256, 1) void gemm_mma(
    const __half* __restrict__ A, const __half* __restrict__ Bt,
    void* __restrict__ Cm, const float* __restrict__ bias,
    const float* __restrict__ res, int M, int N, int K) {
    extern __shared__ uint32_t dynsm[];
    uint32_t* const Abuf[2] = { dynsm, dynsm + GA_U32 };
    uint32_t* const Bbuf[2] = { dynsm + 2 * GA_U32, dynsm + 2 * GA_U32 + GB_U32 };

    const int tid  = threadIdx.x;
    const int wid  = tid >> 5;
    const int lane = tid & 31;
    const int wm   = (wid & 1) * 64;
    const int wn   = (wid >> 1) * 64;
    const int gq   = lane >> 2;
    const int tq   = lane & 3;
    const int brow = blockIdx.y * 128;
    const int bcol = blockIdx.x * 256;

    float acc[4][8][4];
#pragma unroll
    for (int i = 0; i < 4; i++)
#pragma unroll
        for (int j = 0; j < 8; j++)
#pragma unroll
            for (int q = 0; q < 4; q++) acc[i][j][q] = 0.0f;

    const __half* Ag = A + (size_t)brow * K;
    const __half* Bg = Bt + (size_t)bcol * K;
    const int KC = K >> 6;

    const int cr = tid >> 3;
    const int cc = (tid & 7) * 4;

    auto issue = [&](int kc, int s) {
        const __half* Agn = Ag + kc * 64 + cc * 2;
        const __half* Bgn = Bg + kc * 64 + cc * 2;
        uint32_t* As = Abuf[s];
        uint32_t* Bs = Bbuf[s];
#pragma unroll
        for (int i = 0; i < 4; i++) {
            int r = cr + i * 32;
            cp_async16(&As[r * 32 + swz(r, cc)], Agn + (size_t)r * K);
        }
#pragma unroll
        for (int i = 0; i < 8; i++) {
            int r = cr + i * 32;
            cp_async16(&Bs[r * 32 + swz(r, cc)], Bgn + (size_t)r * K);
        }
    };

    issue(0, 0); CP_COMMIT();
    if (KC > 1) issue(1, 1);
    CP_COMMIT();

    for (int kc = 0; kc < KC; kc++) {
        CP_WAIT1();
        __syncthreads();

        uint32_t* As = Abuf[kc & 1];
        uint32_t* Bs = Bbuf[kc & 1];

#pragma unroll
        for (int ks = 0; ks < 4; ks++) {
            const int colA  = (ks * 8 + tq) ^ (8 * (gq & 3)) ^ (4 * ((gq >> 2) & 1));
            const int colA4 = colA ^ 4;

            uint32_t afr[4][4];
#pragma unroll
            for (int mt = 0; mt < 4; mt++) {
                int m0 = wm + mt * 16;
                afr[mt][0] = As[(m0 + gq    ) * 32 + colA ];
                afr[mt][1] = As[(m0 + gq + 8) * 32 + colA ];
                afr[mt][2] = As[(m0 + gq    ) * 32 + colA4];
                afr[mt][3] = As[(m0 + gq + 8) * 32 + colA4];
            }
            uint32_t bfr[8][2];
#pragma unroll
            for (int nt = 0; nt < 8; nt++) {
                int n0 = wn + nt * 8;
                bfr[nt][0] = Bs[(n0 + gq) * 32 + colA ];
                bfr[nt][1] = Bs[(n0 + gq) * 32 + colA4];
            }
#pragma unroll
            for (int mt = 0; mt < 4; mt++)
#pragma unroll
                for (int nt = 0; nt < 8; nt++)
                    mma_f16(acc[mt][nt], afr[mt], bfr[nt], acc[mt][nt]);
        }
        __syncthreads();
        if (kc + 2 < KC) issue(kc + 2, kc & 1);
        CP_COMMIT();
    }

    // epilogue
#pragma unroll
    for (int mt = 0; mt < 4; mt++) {
        int row0 = brow + wm + mt * 16 + gq;
#pragma unroll
        for (int half_ = 0; half_ < 2; half_++) {
            int row = row0 + half_ * 8;
#pragma unroll
            for (int nt = 0; nt < 8; nt++) {
                int col = bcol + wn + nt * 8 + tq * 2;
                float vx = acc[mt][nt][half_ * 2 + 0];
                float vy = acc[mt][nt][half_ * 2 + 1];
                if (EPI == 1 || EPI == 2) {
                    vx += bias[col + 0];
                    vy += bias[col + 1];
                }
                if (EPI == 1) {
                    __half* outr = (__half*)Cm + (size_t)row * N;
                    *(half2*)(outr + col) =
                        __floats2half2_rn(fmaxf(vx, 0.0f), fmaxf(vy, 0.0f));
                } else if (EPI == 3) {
                    __half* outr = (__half*)Cm + (size_t)row * N;
                    *(half2*)(outr + col) = __floats2half2_rn(vx, vy);
                } else {
                    float* outr = (float*)Cm + (size_t)row * N;
                    if (EPI == 2) {
                        float2 rr = *(const float2*)(res + (size_t)row * N + col);
                        vx += rr.x;
                        vy += rr.y;
                    }
                    *(float2*)(outr + col) = make_float2(vx, vy);
                }
            }
        }
    }
}

// ---------------------------------------------------------------------------
// fp16 flash attention with ldmatrix + cp.async, P kept in registers.
// grid (B*H, T/64), 128 threads = 4 warps; warp = 16 query rows.
// Tiles [64 rows][32 halves], row stride 20 u32 (conflict-free LDSM phases).
// Q pre-scaled via weights.
// ---------------------------------------------------------------------------
#define QST 20     // row stride in uint32

__global__ __launch_bounds__(128) void attn_tc_kernel(
    const __half* __restrict__ qkv, __half* __restrict__ att) {
    __shared__ uint32_t smQ[64 * QST];
    __shared__ uint32_t smK[2][64 * QST];
    __shared__ uint32_t smV[2][64 * QST];

    const int bh = blockIdx.x;
    const int b  = bh >> 3;
    const int h  = bh & 7;
    const int qt = blockIdx.y;
    const int tid  = threadIdx.x;
    const int wid  = tid >> 5;
    const int lane = tid & 31;
    const int gq   = lane >> 2;
    const int tq   = lane & 3;
    const int grp  = lane >> 3;
    const int ro   = lane & 7;
    const size_t tokbase = (size_t)b * T_;
    const int qrow0 = qt * 64;
    const int m0 = wid * 16;
    const int ntiles = qt + 1;

    // cp.async K/V tile t into stage s (64 rows x 64 B each)
    auto issue = [&](int t, int s) {
#pragma unroll
        for (int i = 0; i < 2; i++) {
            int e = tid + i * 128;
            int r = e >> 2, c16 = e & 3;
            const __half* kg = qkv + (tokbase + t * 64 + r) * QKV_N + C_ + h * D_ + c16 * 8;
            cp_async16(&smK[s][r * QST + c16 * 4], kg);
            cp_async16(&smV[s][r * QST + c16 * 4], kg + C_);
        }
    };

    issue(0, 0); CP_COMMIT();
    if (ntiles > 1) issue(1, 1);
    CP_COMMIT();

    // Q tile (once, plain loads)
#pragma unroll
    for (int i = 0; i < 2; i++) {
        int e = tid + i * 128;
        int r = e >> 2, c16 = e & 3;
        uint4 v = *(const uint4*)(qkv + (tokbase + qrow0 + r) * QKV_N + h * D_ + c16 * 8);
        *(uint4*)&smQ[r * QST + c16 * 4] = v;
    }
    __syncthreads();

    // Q fragments for both k16-steps (held in regs for the whole loop)
    const uint32_t smQb = (uint32_t)__cvta_generic_to_shared(smQ);
    uint32_t qf[2][4];
#pragma unroll
    for (int ks = 0; ks < 2; ks++) {
        uint32_t a = smQb +
            (((m0 + ro + (grp & 1) * 8) * QST + ks * 8 + (grp >> 1) * 4) << 2);
        ldsm_x4(qf[ks], a);
    }

    const int r0 = qrow0 + m0 + gq;
    const int r1 = r0 + 8;

    float mrow0 = -1e30f, mrow1 = -1e30f;
    float l0 = 0.0f, l1 = 0.0f;
    float o[4][4];
#pragma unroll
    for (int i = 0; i < 4; i++)
#pragma unroll
        for (int j = 0; j < 4; j++) o[i][j] = 0.0f;

    for (int t = 0; t < ntiles; t++) {
        CP_WAIT1();
        __syncthreads();
        const int s = t & 1;
        const uint32_t Kb = (uint32_t)__cvta_generic_to_shared(smK[s]);
        const uint32_t Vb = (uint32_t)__cvta_generic_to_shared(smV[s]);

        // --- S = Q @ K^T (16x64 per warp; 8 LDSM.x4 + 16 mma) ---
        float S[8][4];
#pragma unroll
        for (int nt = 0; nt < 8; nt++)
            S[nt][0] = S[nt][1] = S[nt][2] = S[nt][3] = 0.0f;
#pragma unroll
        for (int ks = 0; ks < 2; ks++) {
#pragma unroll
            for (int nb = 0; nb < 4; nb++) {
                uint32_t kb[4];
                uint32_t a = Kb +
                    (((nb * 16 + ro + (grp >> 1) * 8) * QST + ks * 8 + (grp & 1) * 4) << 2);
                ldsm_x4(kb, a);
                mma_f16v(S[2 * nb    ], qf[ks], kb[0], kb[1], S[2 * nb    ]);
                mma_f16v(S[2 * nb + 1], qf[ks], kb[2], kb[3], S[2 * nb + 1]);
            }
        }

        // --- causal mask (diagonal tile only) ---
        if (t == qt) {
#pragma unroll
            for (int nt = 0; nt < 8; nt++) {
                int col = qrow0 + nt * 8 + 2 * tq;
                if (col     > r0) S[nt][0] = -1e30f;
                if (col + 1 > r0) S[nt][1] = -1e30f;
                if (col     > r1) S[nt][2] = -1e30f;
                if (col + 1 > r1) S[nt][3] = -1e30f;
            }
        }

        // --- online softmax ---
        float mx0 = -1e30f, mx1 = -1e30f;
#pragma unroll
        for (int nt = 0; nt < 8; nt++) {
            mx0 = fmaxf(mx0, fmaxf(S[nt][0], S[nt][1]));
            mx1 = fmaxf(mx1, fmaxf(S[nt][2], S[nt][3]));
        }
        mx0 = fmaxf(mx0, __shfl_xor_sync(0xffffffffu, mx0, 1));
        mx0 = fmaxf(mx0, __shfl_xor_sync(0xffffffffu, mx0, 2));
        mx1 = fmaxf(mx1, __shfl_xor_sync(0xffffffffu, mx1, 1));
        mx1 = fmaxf(mx1, __shfl_xor_sync(0xffffffffu, mx1, 2));

        float mn0 = fmaxf(mrow0, mx0);
        float mn1 = fmaxf(mrow1, mx1);
        float a0 = __expf(mrow0 - mn0);
        float a1 = __expf(mrow1 - mn1);
        mrow0 = mn0;
        mrow1 = mn1;

        float sum0 = 0.0f, sum1 = 0.0f;
#pragma unroll
        for (int nt = 0; nt < 8; nt++) {
            S[nt][0] = __expf(S[nt][0] - mn0);
            S[nt][1] = __expf(S[nt][1] - mn0);
            S[nt][2] = __expf(S[nt][2] - mn1);
            S[nt][3] = __expf(S[nt][3] - mn1);
            sum0 += S[nt][0] + S[nt][1];
            sum1 += S[nt][2] + S[nt][3];
        }
        sum0 += __shfl_xor_sync(0xffffffffu, sum0, 1);
        sum0 += __shfl_xor_sync(0xffffffffu, sum0, 2);
        sum1 += __shfl_xor_sync(0xffffffffu, sum1, 1);
        sum1 += __shfl_xor_sync(0xffffffffu, sum1, 2);
        l0 = l0 * a0 + sum0;
        l1 = l1 * a1 + sum1;

#pragma unroll
        for (int d4 = 0; d4 < 4; d4++) {
            o[d4][0] *= a0;
            o[d4][1] *= a0;
            o[d4][2] *= a1;
            o[d4][3] *= a1;
        }

        // --- P as A-fragments, straight from S registers (no smem) ---
        uint32_t pf[4][4];
#pragma unroll
        for (int kp = 0; kp < 4; kp++) {
            pf[kp][0] = f2h2(S[2 * kp    ][0], S[2 * kp    ][1]);
            pf[kp][1] = f2h2(S[2 * kp    ][2], S[2 * kp    ][3]);
            pf[kp][2] = f2h2(S[2 * kp + 1][0], S[2 * kp + 1][1]);
            pf[kp][3] = f2h2(S[2 * kp + 1][2], S[2 * kp + 1][3]);
        }

        // --- O += P @ V  (V via ldmatrix.trans from [s][d]; 8 LDSM + 16 mma)
#pragma unroll
        for (int j = 0; j < 2; j++) {
#pragma unroll
            for (int kp = 0; kp < 4; kp++) {
                uint32_t vb[4];
                uint32_t a = Vb +
                    (((kp * 16 + ro + (grp & 1) * 8) * QST + (j * 2 + (grp >> 1)) * 4) << 2);
                ldsm_x4_t(vb, a);
                mma_f16v(o[2 * j    ], pf[kp], vb[0], vb[1], o[2 * j    ]);
                mma_f16v(o[2 * j + 1], pf[kp], vb[2], vb[3], o[2 * j + 1]);
            }
        }
        __syncthreads();
        if (t + 2 < ntiles) issue(t + 2, s);
        CP_COMMIT();
    }

    // --- normalize + store fp16 ---
    float inv0 = 1.0f / l0;
    float inv1 = 1.0f / l1;
#pragma unroll
    for (int d4 = 0; d4 < 4; d4++) {
        int col = h * D_ + d4 * 8 + 2 * tq;
        *(half2*)(att + (tokbase + r0) * C_ + col) =
            __floats2half2_rn(o[d4][0] * inv0, o[d4][1] * inv0);
        *(half2*)(att + (tokbase + r1) * C_ + col) =
            __floats2half2_rn(o[d4][2] * inv1, o[d4][3] * inv1);
    }
}

// ---------------------------------------------------------------------------
// Launch
// ---------------------------------------------------------------------------
extern "C" void kernel_launch(void* const* d_in, const int* in_sizes, int n_in,
                              void* d_out, int out_size) {
    const float* x      = (const float*)d_in[0];
    const float* wq     = (const float*)d_in[1];
    const float* wk     = (const float*)d_in[2];
    const float* wv     = (const float*)d_in[3];
    const float* w_proj = (const float*)d_in[4];
    const float* b_proj = (const float*)d_in[5];
    const float* w1     = (const float*)d_in[6];
    const float* b1     = (const float*)d_in[7];
    const float* w2     = (const float*)d_in[8];
    const float* b2     = (const float*)d_in[9];
    const float* ln1_g  = (const float*)d_in[10];
    const float* ln1_b  = (const float*)d_in[11];
    const float* ln2_g  = (const float*)d_in[12];
    const float* ln2_b  = (const float*)d_in[13];
    float* out = (float*)d_out;

    __half *p_h, *p_qkv, *p_att, *p_h2, *p_ffn;
    __half *p_wqkvT, *p_wprojT, *p_w1T, *p_w2T;
    float *p_xmid;
    cudaGetSymbolAddress((void**)&p_h,      g_h);
    cudaGetSymbolAddress((void**)&p_qkv,    g_qkv);
    cudaGetSymbolAddress((void**)&p_att,    g_att);
    cudaGetSymbolAddress((void**)&p_xmid,   g_xmid);
    cudaGetSymbolAddress((void**)&p_h2,     g_h2);
    cudaGetSymbolAddress((void**)&p_ffn,    g_ffn);
    cudaGetSymbolAddress((void**)&p_wqkvT,  g_wqkvT);
    cudaGetSymbolAddress((void**)&p_wprojT, g_wprojT);
    cudaGetSymbolAddress((void**)&p_w1T,    g_w1T);
    cudaGetSymbolAddress((void**)&p_w2T,    g_w2T);

    cudaFuncSetAttribute(gemm_mma<1>, cudaFuncAttributeMaxDynamicSharedMemorySize, GEMM_SMEM_BYTES);
    cudaFuncSetAttribute(gemm_mma<2>, cudaFuncAttributeMaxDynamicSharedMemorySize, GEMM_SMEM_BYTES);
    cudaFuncSetAttribute(gemm_mma<3>, cudaFuncAttributeMaxDynamicSharedMemorySize, GEMM_SMEM_BYTES);

    // weight prep
    prep_weights_kernel<<<(PREP_TOTAL + 255) / 256, 256>>>(
        wq, wk, wv, w_proj, w1, w2, p_wqkvT, p_wprojT, p_w1T, p_w2T);

    // 1. h = ln1(x)                       (fp16)
    layernorm_kernel<<<M_TOK / 8, 256>>>(x, ln1_g, ln1_b, p_h);

    // 2. qkv = h @ Wqkv                   (fp16 out; q pre-scaled)
    gemm_mma<3><<<dim3(QKV_N / 256, M_TOK / 128), 256, GEMM_SMEM_BYTES>>>(
        p_h, p_wqkvT, p_qkv, nullptr, nullptr, M_TOK, QKV_N, C_);

    // 3. causal attention                 (fp16 in/out)
    attn_tc_kernel<<<dim3(B_ * H_, T_ / 64), 128>>>(p_qkv, p_att);

    // 4. xmid = x + att @ w_proj + b_proj (fp32)
    gemm_mma<2><<<dim3(C_ / 256, M_TOK / 128), 256, GEMM_SMEM_BYTES>>>(
        p_att, p_wprojT, p_xmid, b_proj, x, M_TOK, C_, C_);

    // 5. h2 = ln2(xmid)                   (fp16)
    layernorm_kernel<<<M_TOK / 8, 256>>>(p_xmid, ln2_g, ln2_b, p_h2);

    // 6. ffn = relu(h2 @ w1 + b1)         (fp16)
    gemm_mma<1><<<dim3(FF_ / 256, M_TOK / 128), 256, GEMM_SMEM_BYTES>>>(
        p_h2, p_w1T, p_ffn, b1, nullptr, M_TOK, FF_, C_);

    // 7. out = xmid + ffn @ w2 + b2       (fp32)
    gemm_mma<2><<<dim3(C_ / 256, M_TOK / 128), 256, GEMM_SMEM_BYTES>>>(
        p_ffn, p_w2T, out, b2, p_xmid, M_TOK, C_, FF_);
}

// round 12
// speedup vs baseline: 2.0530x; 1.0776x over previous
#include <cuda_runtime.h>
#include <cuda_fp16.h>
#include <cstdint>

// Problem constants
#define B_    16
#define T_    1024
#define C_    256
#define H_    8
#define D_    32
#define M_TOK (B_ * T_)      // 16384 tokens
#define FF_   (4 * C_)       // 1024
#define QKV_N (3 * C_)       // 768
#define ATT_SCALE 0.0625f
#define LN_EPS 1e-5f

// ---------------------------------------------------------------------------
// Scratch (device globals)
// ---------------------------------------------------------------------------
__device__ __half g_h     [M_TOK * C_];     // ln1 output (fp16)
__device__ __half g_qkv   [M_TOK * QKV_N];  // q|k|v (fp16; q pre-scaled)
__device__ __half g_att   [M_TOK * C_];     // attention output (fp16)
__device__ float  g_xmid  [M_TOK * C_];     // x + attn proj (fp32)
__device__ __half g_h2    [M_TOK * C_];     // ln2 output (fp16)
__device__ __half g_ffn   [M_TOK * FF_];    // relu(h2@w1+b1) (fp16)
__device__ __half g_wqkvT [QKV_N * C_];     // [N=768][K=256]; q cols scaled
__device__ __half g_wprojT[C_ * C_];
__device__ __half g_w1T   [FF_ * C_];
__device__ __half g_w2T   [C_ * FF_];

// ---------------------------------------------------------------------------
// Small helpers
// ---------------------------------------------------------------------------
__device__ __forceinline__ void mma_f16(float* d,
                                        const uint32_t* a, const uint32_t* b,
                                        const float* c) {
    asm volatile(
        "mma.sync.aligned.m16n8k16.row.col.f32.f16.f16.f32 "
        "{%0,%1,%2,%3}, {%4,%5,%6,%7}, {%8,%9}, {%10,%11,%12,%13};"
        : "=f"(d[0]), "=f"(d[1]), "=f"(d[2]), "=f"(d[3])
        : "r"(a[0]), "r"(a[1]), "r"(a[2]), "r"(a[3]),
          "r"(b[0]), "r"(b[1]),
          "f"(c[0]), "f"(c[1]), "f"(c[2]), "f"(c[3]));
}
__device__ __forceinline__ void mma_f16v(float* d, const uint32_t* a,
                                         uint32_t b0, uint32_t b1,
                                         const float* c) {
    asm volatile(
        "mma.sync.aligned.m16n8k16.row.col.f32.f16.f16.f32 "
        "{%0,%1,%2,%3}, {%4,%5,%6,%7}, {%8,%9}, {%10,%11,%12,%13};"
        : "=f"(d[0]), "=f"(d[1]), "=f"(d[2]), "=f"(d[3])
        : "r"(a[0]), "r"(a[1]), "r"(a[2]), "r"(a[3]),
          "r"(b0), "r"(b1),
          "f"(c[0]), "f"(c[1]), "f"(c[2]), "f"(c[3]));
}
__device__ __forceinline__ void ldsm_x4(uint32_t* r, uint32_t a) {
    asm volatile("ldmatrix.sync.aligned.m8n8.x4.shared.b16 {%0,%1,%2,%3}, [%4];"
                 : "=r"(r[0]), "=r"(r[1]), "=r"(r[2]), "=r"(r[3]) : "r"(a));
}
__device__ __forceinline__ void ldsm_x4_t(uint32_t* r, uint32_t a) {
    asm volatile("ldmatrix.sync.aligned.m8n8.x4.trans.shared.b16 {%0,%1,%2,%3}, [%4];"
                 : "=r"(r[0]), "=r"(r[1]), "=r"(r[2]), "=r"(r[3]) : "r"(a));
}
__device__ __forceinline__ uint32_t f2h2(float x, float y) {
    half2 h = __floats2half2_rn(x, y);
    return *reinterpret_cast<uint32_t*>(&h);
}
// swizzled column (uint32 units) for element (row, col) in a [rows][32u32] tile
__device__ __forceinline__ int swz(int row, int k) {
    return k ^ (8 * (row & 3)) ^ (4 * ((row >> 2) & 1));
}
__device__ __forceinline__ void cp_async16(void* sp, const void* gp) {
    uint32_t sa = (uint32_t)__cvta_generic_to_shared(sp);
    asm volatile("cp.async.cg.shared.global [%0], [%1], 16;"
                 :: "r"(sa), "l"(gp) : "memory");
}
#define CP_COMMIT() asm volatile("cp.async.commit_group;" ::: "memory")
#define CP_WAIT1()  asm volatile("cp.async.wait_group 1;" ::: "memory")

// ---------------------------------------------------------------------------
// Weight prep (fp16 outputs; q columns pre-scaled by ATT_SCALE)
// ---------------------------------------------------------------------------
#define PREP_TOTAL (QKV_N * C_ + C_ * C_ + C_ * FF_ + FF_ * C_)

__global__ void prep_weights_kernel(
    const float* __restrict__ wq, const float* __restrict__ wk,
    const float* __restrict__ wv, const float* __restrict__ w_proj,
    const float* __restrict__ w1, const float* __restrict__ w2,
    __half* __restrict__ wqkvT, __half* __restrict__ wprojT,
    __half* __restrict__ w1T, __half* __restrict__ w2T) {
    int i = blockIdx.x * blockDim.x + threadIdx.x;
    if (i < QKV_N * C_) {
        int n = i / C_;
        int c = i % C_;
        const float* w = (n < C_) ? wq : ((n < 2 * C_) ? wk : wv);
        int nn = n & (C_ - 1);
        float val = w[((size_t)(nn >> 5) * C_ + c) * D_ + (nn & 31)];
        if (n < C_) val *= ATT_SCALE;
        wqkvT[i] = __float2half_rn(val);
        return;
    }
    i -= QKV_N * C_;
    if (i < C_ * C_) {
        int r = i / C_, c = i % C_;
        wprojT[c * C_ + r] = __float2half_rn(w_proj[i]);
        return;
    }
    i -= C_ * C_;
    if (i < C_ * FF_) {
        int r = i / FF_, c = i % FF_;
        w1T[c * C_ + r] = __float2half_rn(w1[i]);
        return;
    }
    i -= C_ * FF_;
    if (i < FF_ * C_) {
        int r = i / C_, c = i % C_;
        w2T[c * FF_ + r] = __float2half_rn(w2[i]);
    }
}

// ---------------------------------------------------------------------------
// LayerNorm: one warp per 256-float row; OUTPUT fp16
// ---------------------------------------------------------------------------
__global__ __launch_bounds__(256) void layernorm_kernel(
    const float* __restrict__ in, const float* __restrict__ g,
    const float* __restrict__ b, __half* __restrict__ out) {
    int warp = threadIdx.x >> 5;
    int lane = threadIdx.x & 31;
    int row  = blockIdx.x * 8 + warp;

    const float4* rp = (const float4*)(in + (size_t)row * C_);
    float4 v0 = rp[lane];
    float4 v1 = rp[lane + 32];

    float s  = v0.x + v0.y + v0.z + v0.w + v1.x + v1.y + v1.z + v1.w;
    float ss = v0.x * v0.x + v0.y * v0.y + v0.z * v0.z + v0.w * v0.w
             + v1.x * v1.x + v1.y * v1.y + v1.z * v1.z + v1.w * v1.w;
#pragma unroll
    for (int off = 16; off; off >>= 1) {
        s  += __shfl_xor_sync(0xffffffffu, s,  off);
        ss += __shfl_xor_sync(0xffffffffu, ss, off);
    }
    float mean = s * (1.0f / C_);
    float var  = ss * (1.0f / C_) - mean * mean;
    float inv  = rsqrtf(var + LN_EPS);

    const float4* gp = (const float4*)g;
    const float4* bp = (const float4*)b;
    float4 g0 = gp[lane], g1 = gp[lane + 32];
    float4 b0 = bp[lane], b1 = bp[lane + 32];

    half2 h0a = __floats2half2_rn((v0.x - mean) * inv * g0.x + b0.x,
                                  (v0.y - mean) * inv * g0.y + b0.y);
    half2 h0b = __floats2half2_rn((v0.z - mean) * inv * g0.z + b0.z,
                                  (v0.w - mean) * inv * g0.w + b0.w);
    half2 h1a = __floats2half2_rn((v1.x - mean) * inv * g1.x + b1.x,
                                  (v1.y - mean) * inv * g1.y + b1.y);
    half2 h1b = __floats2half2_rn((v1.z - mean) * inv * g1.z + b1.z,
                                  (v1.w - mean) * inv * g1.w + b1.w);

    half2* op = (half2*)(out + (size_t)row * C_);
    op[lane * 2 + 0]  = h0a;
    op[lane * 2 + 1]  = h0b;
    op[lane * 2 + 64] = h1a;
    op[lane * 2 + 65] = h1b;
}

// ---------------------------------------------------------------------------
// fp16 mma.sync GEMM (m16n8k16): cp.async pipeline + ldmatrix fragments.
// CTA tile 128x256, K-chunk 64 halves, 8 warps (2m x 4n), warp tile 64x64.
// EPI: 0 = plain fp32, 1 = +bias+relu fp16, 2 = +bias+residual fp32,
//      3 = plain fp16
// ---------------------------------------------------------------------------
#define GA_U32 (128 * 32)
#define GB_U32 (256 * 32)
#define GEMM_SMEM_BYTES (2 * (GA_U32 + GB_U32) * 4)   // 98304

template <int EPI>
__global__ __launch_bounds__(256, 1) void gemm_mma(
    const __half* __restrict__ A, const __half* __restrict__ Bt,
    void* __restrict__ Cm, const float* __restrict__ bias,
    const float* __restrict__ res, int M, int N, int K) {
    extern __shared__ uint32_t dynsm[];
    uint32_t* const Abuf[2] = { dynsm, dynsm + GA_U32 };
    uint32_t* const Bbuf[2] = { dynsm + 2 * GA_U32, dynsm + 2 * GA_U32 + GB_U32 };

    const int tid  = threadIdx.x;
    const int wid  = tid >> 5;
    const int lane = tid & 31;
    const int wm   = (wid & 1) * 64;
    const int wn   = (wid >> 1) * 64;
    const int gq   = lane >> 2;
    const int tq   = lane & 3;
    const int grp  = lane >> 3;      // 0..3 lane-group for ldmatrix
    const int ro   = lane & 7;
    const int brow = blockIdx.y * 128;
    const int bcol = blockIdx.x * 256;

    float acc[4][8][4];
#pragma unroll
    for (int i = 0; i < 4; i++)
#pragma unroll
        for (int j = 0; j < 8; j++)
#pragma unroll
            for (int q = 0; q < 4; q++) acc[i][j][q] = 0.0f;

    const __half* Ag = A + (size_t)brow * K;
    const __half* Bg = Bt + (size_t)bcol * K;
    const int KC = K >> 6;

    const int cr = tid >> 3;
    const int cc = (tid & 7) * 4;

    auto issue = [&](int kc, int s) {
        const __half* Agn = Ag + kc * 64 + cc * 2;
        const __half* Bgn = Bg + kc * 64 + cc * 2;
        uint32_t* As = Abuf[s];
        uint32_t* Bs = Bbuf[s];
#pragma unroll
        for (int i = 0; i < 4; i++) {
            int r = cr + i * 32;
            cp_async16(&As[r * 32 + swz(r, cc)], Agn + (size_t)r * K);
        }
#pragma unroll
        for (int i = 0; i < 8; i++) {
            int r = cr + i * 32;
            cp_async16(&Bs[r * 32 + swz(r, cc)], Bgn + (size_t)r * K);
        }
    };

    issue(0, 0); CP_COMMIT();
    if (KC > 1) issue(1, 1);
    CP_COMMIT();

    // ldmatrix lane addressing (rows/cols within the CTA tile):
    //  A: row = m0 + ro + (grp&1)*8 , colbase = ks*8 + (grp>>1)*4
    //  B: row = n0 + ro + (grp>>1)*8, colbase = ks*8 + (grp&1)*4
    const int arow_lo = ro + (grp & 1) * 8;     // + m0
    const int acol_off = (grp >> 1) * 4;        // + ks*8
    const int brow_lo = ro + (grp >> 1) * 8;    // + n0
    const int bcol_off = (grp & 1) * 4;         // + ks*8

    for (int kc = 0; kc < KC; kc++) {
        CP_WAIT1();
        __syncthreads();

        const uint32_t Ab = (uint32_t)__cvta_generic_to_shared(Abuf[kc & 1]);
        const uint32_t Bb = (uint32_t)__cvta_generic_to_shared(Bbuf[kc & 1]);

#pragma unroll
        for (int ks = 0; ks < 4; ks++) {
            uint32_t afr[4][4];
#pragma unroll
            for (int mt = 0; mt < 4; mt++) {
                int row = wm + mt * 16 + arow_lo;
                uint32_t a = Ab + ((row * 32 + swz(row, ks * 8 + acol_off)) << 2);
                ldsm_x4(afr[mt], a);
            }
#pragma unroll
            for (int nb = 0; nb < 4; nb++) {
                int row = wn + nb * 16 + brow_lo;
                uint32_t a = Bb + ((row * 32 + swz(row, ks * 8 + bcol_off)) << 2);
                uint32_t kb[4];
                ldsm_x4(kb, a);
#pragma unroll
                for (int mt = 0; mt < 4; mt++) {
                    mma_f16v(acc[mt][2 * nb    ], afr[mt], kb[0], kb[1],
                             acc[mt][2 * nb    ]);
                    mma_f16v(acc[mt][2 * nb + 1], afr[mt], kb[2], kb[3],
                             acc[mt][2 * nb + 1]);
                }
            }
        }
        __syncthreads();
        if (kc + 2 < KC) issue(kc + 2, kc & 1);
        CP_COMMIT();
    }

    // epilogue
#pragma unroll
    for (int mt = 0; mt < 4; mt++) {
        int row0 = brow + wm + mt * 16 + gq;
#pragma unroll
        for (int half_ = 0; half_ < 2; half_++) {
            int row = row0 + half_ * 8;
#pragma unroll
            for (int nt = 0; nt < 8; nt++) {
                int col = bcol + wn + nt * 8 + tq * 2;
                float vx = acc[mt][nt][half_ * 2 + 0];
                float vy = acc[mt][nt][half_ * 2 + 1];
                if (EPI == 1 || EPI == 2) {
                    vx += bias[col + 0];
                    vy += bias[col + 1];
                }
                if (EPI == 1) {
                    __half* outr = (__half*)Cm + (size_t)row * N;
                    *(half2*)(outr + col) =
                        __floats2half2_rn(fmaxf(vx, 0.0f), fmaxf(vy, 0.0f));
                } else if (EPI == 3) {
                    __half* outr = (__half*)Cm + (size_t)row * N;
                    *(half2*)(outr + col) = __floats2half2_rn(vx, vy);
                } else {
                    float* outr = (float*)Cm + (size_t)row * N;
                    if (EPI == 2) {
                        float2 rr = *(const float2*)(res + (size_t)row * N + col);
                        vx += rr.x;
                        vy += rr.y;
                    }
                    *(float2*)(outr + col) = make_float2(vx, vy);
                }
            }
        }
    }
}

// ---------------------------------------------------------------------------
// fp16 flash attention with ldmatrix + cp.async, P kept in registers.
// (unchanged from R11 winner)
// ---------------------------------------------------------------------------
#define QST 20     // row stride in uint32

__global__ __launch_bounds__(128) void attn_tc_kernel(
    const __half* __restrict__ qkv, __half* __restrict__ att) {
    __shared__ uint32_t smQ[64 * QST];
    __shared__ uint32_t smK[2][64 * QST];
    __shared__ uint32_t smV[2][64 * QST];

    const int bh = blockIdx.x;
    const int b  = bh >> 3;
    const int h  = bh & 7;
    const int qt = blockIdx.y;
    const int tid  = threadIdx.x;
    const int wid  = tid >> 5;
    const int lane = tid & 31;
    const int gq   = lane >> 2;
    const int tq   = lane & 3;
    const int grp  = lane >> 3;
    const int ro   = lane & 7;
    const size_t tokbase = (size_t)b * T_;
    const int qrow0 = qt * 64;
    const int m0 = wid * 16;
    const int ntiles = qt + 1;

    auto issue = [&](int t, int s) {
#pragma unroll
        for (int i = 0; i < 2; i++) {
            int e = tid + i * 128;
            int r = e >> 2, c16 = e & 3;
            const __half* kg = qkv + (tokbase + t * 64 + r) * QKV_N + C_ + h * D_ + c16 * 8;
            cp_async16(&smK[s][r * QST + c16 * 4], kg);
            cp_async16(&smV[s][r * QST + c16 * 4], kg + C_);
        }
    };

    issue(0, 0); CP_COMMIT();
    if (ntiles > 1) issue(1, 1);
    CP_COMMIT();

#pragma unroll
    for (int i = 0; i < 2; i++) {
        int e = tid + i * 128;
        int r = e >> 2, c16 = e & 3;
        uint4 v = *(const uint4*)(qkv + (tokbase + qrow0 + r) * QKV_N + h * D_ + c16 * 8);
        *(uint4*)&smQ[r * QST + c16 * 4] = v;
    }
    __syncthreads();

    const uint32_t smQb = (uint32_t)__cvta_generic_to_shared(smQ);
    uint32_t qf[2][4];
#pragma unroll
    for (int ks = 0; ks < 2; ks++) {
        uint32_t a = smQb +
            (((m0 + ro + (grp & 1) * 8) * QST + ks * 8 + (grp >> 1) * 4) << 2);
        ldsm_x4(qf[ks], a);
    }

    const int r0 = qrow0 + m0 + gq;
    const int r1 = r0 + 8;

    float mrow0 = -1e30f, mrow1 = -1e30f;
    float l0 = 0.0f, l1 = 0.0f;
    float o[4][4];
#pragma unroll
    for (int i = 0; i < 4; i++)
#pragma unroll
        for (int j = 0; j < 4; j++) o[i][j] = 0.0f;

    for (int t = 0; t < ntiles; t++) {
        CP_WAIT1();
        __syncthreads();
        const int s = t & 1;
        const uint32_t Kb = (uint32_t)__cvta_generic_to_shared(smK[s]);
        const uint32_t Vb = (uint32_t)__cvta_generic_to_shared(smV[s]);

        float S[8][4];
#pragma unroll
        for (int nt = 0; nt < 8; nt++)
            S[nt][0] = S[nt][1] = S[nt][2] = S[nt][3] = 0.0f;
#pragma unroll
        for (int ks = 0; ks < 2; ks++) {
#pragma unroll
            for (int nb = 0; nb < 4; nb++) {
                uint32_t kb[4];
                uint32_t a = Kb +
                    (((nb * 16 + ro + (grp >> 1) * 8) * QST + ks * 8 + (grp & 1) * 4) << 2);
                ldsm_x4(kb, a);
                mma_f16v(S[2 * nb    ], qf[ks], kb[0], kb[1], S[2 * nb    ]);
                mma_f16v(S[2 * nb + 1], qf[ks], kb[2], kb[3], S[2 * nb + 1]);
            }
        }

        if (t == qt) {
#pragma unroll
            for (int nt = 0; nt < 8; nt++) {
                int col = qrow0 + nt * 8 + 2 * tq;
                if (col     > r0) S[nt][0] = -1e30f;
                if (col + 1 > r0) S[nt][1] = -1e30f;
                if (col     > r1) S[nt][2] = -1e30f;
                if (col + 1 > r1) S[nt][3] = -1e30f;
            }
        }

        float mx0 = -1e30f, mx1 = -1e30f;
#pragma unroll
        for (int nt = 0; nt < 8; nt++) {
            mx0 = fmaxf(mx0, fmaxf(S[nt][0], S[nt][1]));
            mx1 = fmaxf(mx1, fmaxf(S[nt][2], S[nt][3]));
        }
        mx0 = fmaxf(mx0, __shfl_xor_sync(0xffffffffu, mx0, 1));
        mx0 = fmaxf(mx0, __shfl_xor_sync(0xffffffffu, mx0, 2));
        mx1 = fmaxf(mx1, __shfl_xor_sync(0xffffffffu, mx1, 1));
        mx1 = fmaxf(mx1, __shfl_xor_sync(0xffffffffu, mx1, 2));

        float mn0 = fmaxf(mrow0, mx0);
        float mn1 = fmaxf(mrow1, mx1);
        float a0 = __expf(mrow0 - mn0);
        float a1 = __expf(mrow1 - mn1);
        mrow0 = mn0;
        mrow1 = mn1;

        float sum0 = 0.0f, sum1 = 0.0f;
#pragma unroll
        for (int nt = 0; nt < 8; nt++) {
            S[nt][0] = __expf(S[nt][0] - mn0);
            S[nt][1] = __expf(S[nt][1] - mn0);
            S[nt][2] = __expf(S[nt][2] - mn1);
            S[nt][3] = __expf(S[nt][3] - mn1);
            sum0 += S[nt][0] + S[nt][1];
            sum1 += S[nt][2] + S[nt][3];
        }
        sum0 += __shfl_xor_sync(0xffffffffu, sum0, 1);
        sum0 += __shfl_xor_sync(0xffffffffu, sum0, 2);
        sum1 += __shfl_xor_sync(0xffffffffu, sum1, 1);
        sum1 += __shfl_xor_sync(0xffffffffu, sum1, 2);
        l0 = l0 * a0 + sum0;
        l1 = l1 * a1 + sum1;

#pragma unroll
        for (int d4 = 0; d4 < 4; d4++) {
            o[d4][0] *= a0;
            o[d4][1] *= a0;
            o[d4][2] *= a1;
            o[d4][3] *= a1;
        }

        uint32_t pf[4][4];
#pragma unroll
        for (int kp = 0; kp < 4; kp++) {
            pf[kp][0] = f2h2(S[2 * kp    ][0], S[2 * kp    ][1]);
            pf[kp][1] = f2h2(S[2 * kp    ][2], S[2 * kp    ][3]);
            pf[kp][2] = f2h2(S[2 * kp + 1][0], S[2 * kp + 1][1]);
            pf[kp][3] = f2h2(S[2 * kp + 1][2], S[2 * kp + 1][3]);
        }

#pragma unroll
        for (int j = 0; j < 2; j++) {
#pragma unroll
            for (int kp = 0; kp < 4; kp++) {
                uint32_t vb[4];
                uint32_t a = Vb +
                    (((kp * 16 + ro + (grp & 1) * 8) * QST + (j * 2 + (grp >> 1)) * 4) << 2);
                ldsm_x4_t(vb, a);
                mma_f16v(o[2 * j    ], pf[kp], vb[0], vb[1], o[2 * j    ]);
                mma_f16v(o[2 * j + 1], pf[kp], vb[2], vb[3], o[2 * j + 1]);
            }
        }
        __syncthreads();
        if (t + 2 < ntiles) issue(t + 2, s);
        CP_COMMIT();
    }

    float inv0 = 1.0f / l0;
    float inv1 = 1.0f / l1;
#pragma unroll
    for (int d4 = 0; d4 < 4; d4++) {
        int col = h * D_ + d4 * 8 + 2 * tq;
        *(half2*)(att + (tokbase + r0) * C_ + col) =
            __floats2half2_rn(o[d4][0] * inv0, o[d4][1] * inv0);
        *(half2*)(att + (tokbase + r1) * C_ + col) =
            __floats2half2_rn(o[d4][2] * inv1, o[d4][3] * inv1);
    }
}

// ---------------------------------------------------------------------------
// Launch
// ---------------------------------------------------------------------------
extern "C" void kernel_launch(void* const* d_in, const int* in_sizes, int n_in,
                              void* d_out, int out_size) {
    const float* x      = (const float*)d_in[0];
    const float* wq     = (const float*)d_in[1];
    const float* wk     = (const float*)d_in[2];
    const float* wv     = (const float*)d_in[3];
    const float* w_proj = (const float*)d_in[4];
    const float* b_proj = (const float*)d_in[5];
    const float* w1     = (const float*)d_in[6];
    const float* b1     = (const float*)d_in[7];
    const float* w2     = (const float*)d_in[8];
    const float* b2     = (const float*)d_in[9];
    const float* ln1_g  = (const float*)d_in[10];
    const float* ln1_b  = (const float*)d_in[11];
    const float* ln2_g  = (const float*)d_in[12];
    const float* ln2_b  = (const float*)d_in[13];
    float* out = (float*)d_out;

    __half *p_h, *p_qkv, *p_att, *p_h2, *p_ffn;
    __half *p_wqkvT, *p_wprojT, *p_w1T, *p_w2T;
    float *p_xmid;
    cudaGetSymbolAddress((void**)&p_h,      g_h);
    cudaGetSymbolAddress((void**)&p_qkv,    g_qkv);
    cudaGetSymbolAddress((void**)&p_att,    g_att);
    cudaGetSymbolAddress((void**)&p_xmid,   g_xmid);
    cudaGetSymbolAddress((void**)&p_h2,     g_h2);
    cudaGetSymbolAddress((void**)&p_ffn,    g_ffn);
    cudaGetSymbolAddress((void**)&p_wqkvT,  g_wqkvT);
    cudaGetSymbolAddress((void**)&p_wprojT, g_wprojT);
    cudaGetSymbolAddress((void**)&p_w1T,    g_w1T);
    cudaGetSymbolAddress((void**)&p_w2T,    g_w2T);

    cudaFuncSetAttribute(gemm_mma<1>, cudaFuncAttributeMaxDynamicSharedMemorySize, GEMM_SMEM_BYTES);
    cudaFuncSetAttribute(gemm_mma<2>, cudaFuncAttributeMaxDynamicSharedMemorySize, GEMM_SMEM_BYTES);
    cudaFuncSetAttribute(gemm_mma<3>, cudaFuncAttributeMaxDynamicSharedMemorySize, GEMM_SMEM_BYTES);

    // weight prep
    prep_weights_kernel<<<(PREP_TOTAL + 255) / 256, 256>>>(
        wq, wk, wv, w_proj, w1, w2, p_wqkvT, p_wprojT, p_w1T, p_w2T);

    // 1. h = ln1(x)                       (fp16)
    layernorm_kernel<<<M_TOK / 8, 256>>>(x, ln1_g, ln1_b, p_h);

    // 2. qkv = h @ Wqkv                   (fp16 out; q pre-scaled)
    gemm_mma<3><<<dim3(QKV_N / 256, M_TOK / 128), 256, GEMM_SMEM_BYTES>>>(
        p_h, p_wqkvT, p_qkv, nullptr, nullptr, M_TOK, QKV_N, C_);

    // 3. causal attention                 (fp16 in/out)
    attn_tc_kernel<<<dim3(B_ * H_, T_ / 64), 128>>>(p_qkv, p_att);

    // 4. xmid = x + att @ w_proj + b_proj (fp32)
    gemm_mma<2><<<dim3(C_ / 256, M_TOK / 128), 256, GEMM_SMEM_BYTES>>>(
        p_att, p_wprojT, p_xmid, b_proj, x, M_TOK, C_, C_);

    // 5. h2 = ln2(xmid)                   (fp16)
    layernorm_kernel<<<M_TOK / 8, 256>>>(p_xmid, ln2_g, ln2_b, p_h2);

    // 6. ffn = relu(h2 @ w1 + b1)         (fp16)
    gemm_mma<1><<<dim3(FF_ / 256, M_TOK / 128), 256, GEMM_SMEM_BYTES>>>(
        p_h2, p_w1T, p_ffn, b1, nullptr, M_TOK, FF_, C_);

    // 7. out = xmid + ffn @ w2 + b2       (fp32)
    gemm_mma<2><<<dim3(C_ / 256, M_TOK / 128), 256, GEMM_SMEM_BYTES>>>(
        p_ffn, p_w2T, out, b2, p_xmid, M_TOK, C_, FF_);
}

// round 17
// speedup vs baseline: 2.0995x; 1.0227x over previous
#include <cuda_runtime.h>
#include <cuda_fp16.h>
#include <cstdint>

// Problem constants
#define B_    16
#define T_    1024
#define C_    256
#define H_    8
#define D_    32
#define M_TOK (B_ * T_)      // 16384 tokens
#define FF_   (4 * C_)       // 1024
#define QKV_N (3 * C_)       // 768
#define ATT_SCALE 0.0625f
#define LOG2E 1.44269504088896f
#define LN_EPS 1e-5f

// ---------------------------------------------------------------------------
// Scratch (device globals)
// ---------------------------------------------------------------------------
__device__ __half g_h     [M_TOK * C_];     // ln1 output (fp16)
__device__ __half g_qkv   [M_TOK * QKV_N];  // q|k|v (fp16; q pre-scaled*log2e)
__device__ __half g_att   [M_TOK * C_];     // attention output (fp16)
__device__ float  g_xmid  [M_TOK * C_];     // x + attn proj (fp32)
__device__ __half g_h2    [M_TOK * C_];     // ln2 output (fp16)
__device__ __half g_ffn   [M_TOK * FF_];    // relu(h2@w1+b1) (fp16)
__device__ __half g_wqkvT [QKV_N * C_];     // [N=768][K=256]
__device__ __half g_wprojT[C_ * C_];
__device__ __half g_w1T   [FF_ * C_];
__device__ __half g_w2T   [C_ * FF_];

// ---------------------------------------------------------------------------
// Small helpers
// ---------------------------------------------------------------------------
__device__ __forceinline__ void mma_f16v(float* d, const uint32_t* a,
                                         uint32_t b0, uint32_t b1,
                                         const float* c) {
    asm volatile(
        "mma.sync.aligned.m16n8k16.row.col.f32.f16.f16.f32 "
        "{%0,%1,%2,%3}, {%4,%5,%6,%7}, {%8,%9}, {%10,%11,%12,%13};"
        : "=f"(d[0]), "=f"(d[1]), "=f"(d[2]), "=f"(d[3])
        : "r"(a[0]), "r"(a[1]), "r"(a[2]), "r"(a[3]),
          "r"(b0), "r"(b1),
          "f"(c[0]), "f"(c[1]), "f"(c[2]), "f"(c[3]));
}
__device__ __forceinline__ void ldsm_x4(uint32_t* r, uint32_t a) {
    asm volatile("ldmatrix.sync.aligned.m8n8.x4.shared.b16 {%0,%1,%2,%3}, [%4];"
                 : "=r"(r[0]), "=r"(r[1]), "=r"(r[2]), "=r"(r[3]) : "r"(a));
}
__device__ __forceinline__ void ldsm_x4_t(uint32_t* r, uint32_t a) {
    asm volatile("ldmatrix.sync.aligned.m8n8.x4.trans.shared.b16 {%0,%1,%2,%3}, [%4];"
                 : "=r"(r[0]), "=r"(r[1]), "=r"(r[2]), "=r"(r[3]) : "r"(a));
}
__device__ __forceinline__ uint32_t f2h2(float x, float y) {
    half2 h = __floats2half2_rn(x, y);
    return *reinterpret_cast<uint32_t*>(&h);
}
// swizzled column (uint32 units) for element (row, col) in a [rows][32u32] tile
__device__ __forceinline__ int swz(int row, int k) {
    return k ^ (8 * (row & 3)) ^ (4 * ((row >> 2) & 1));
}
__device__ __forceinline__ void cp_async16(void* sp, const void* gp) {
    uint32_t sa = (uint32_t)__cvta_generic_to_shared(sp);
    asm volatile("cp.async.cg.shared.global [%0], [%1], 16;"
                 :: "r"(sa), "l"(gp) : "memory");
}
#define CP_COMMIT() asm volatile("cp.async.commit_group;" ::: "memory")
#define CP_WAIT1()  asm volatile("cp.async.wait_group 1;" ::: "memory")

// ---------------------------------------------------------------------------
// Weight prep (fp16; q columns pre-scaled by ATT_SCALE*log2e for exp2 softmax)
// ---------------------------------------------------------------------------
#define PREP_TOTAL (QKV_N * C_ + C_ * C_ + C_ * FF_ + FF_ * C_)

__global__ void prep_weights_kernel(
    const float* __restrict__ wq, const float* __restrict__ wk,
    const float* __restrict__ wv, const float* __restrict__ w_proj,
    const float* __restrict__ w1, const float* __restrict__ w2,
    __half* __restrict__ wqkvT, __half* __restrict__ wprojT,
    __half* __restrict__ w1T, __half* __restrict__ w2T) {
    int i = blockIdx.x * blockDim.x + threadIdx.x;
    if (i < QKV_N * C_) {
        int n = i / C_;
        int c = i % C_;
        const float* w = (n < C_) ? wq : ((n < 2 * C_) ? wk : wv);
        int nn = n & (C_ - 1);
        float val = w[((size_t)(nn >> 5) * C_ + c) * D_ + (nn & 31)];
        if (n < C_) val *= ATT_SCALE * LOG2E;   // scores in log2 domain
        wqkvT[i] = __float2half_rn(val);
        return;
    }
    i -= QKV_N * C_;
    if (i < C_ * C_) {
        int r = i / C_, c = i % C_;
        wprojT[c * C_ + r] = __float2half_rn(w_proj[i]);
        return;
    }
    i -= C_ * C_;
    if (i < C_ * FF_) {
        int r = i / FF_, c = i % FF_;
        w1T[c * C_ + r] = __float2half_rn(w1[i]);
        return;
    }
    i -= C_ * FF_;
    if (i < FF_ * C_) {
        int r = i / C_, c = i % C_;
        w2T[c * FF_ + r] = __float2half_rn(w2[i]);
    }
}

// ---------------------------------------------------------------------------
// LayerNorm: one warp per 256-float row; OUTPUT fp16
// ---------------------------------------------------------------------------
__global__ __launch_bounds__(256) void layernorm_kernel(
    const float* __restrict__ in, const float* __restrict__ g,
    const float* __restrict__ b, __half* __restrict__ out) {
    int warp = threadIdx.x >> 5;
    int lane = threadIdx.x & 31;
    int row  = blockIdx.x * 8 + warp;

    const float4* rp = (const float4*)(in + (size_t)row * C_);
    float4 v0 = rp[lane];
    float4 v1 = rp[lane + 32];

    float s  = v0.x + v0.y + v0.z + v0.w + v1.x + v1.y + v1.z + v1.w;
    float ss = v0.x * v0.x + v0.y * v0.y + v0.z * v0.z + v0.w * v0.w
             + v1.x * v1.x + v1.y * v1.y + v1.z * v1.z + v1.w * v1.w;
#pragma unroll
    for (int off = 16; off; off >>= 1) {
        s  += __shfl_xor_sync(0xffffffffu, s,  off);
        ss += __shfl_xor_sync(0xffffffffu, ss, off);
    }
    float mean = s * (1.0f / C_);
    float var  = ss * (1.0f / C_) - mean * mean;
    float inv  = rsqrtf(var + LN_EPS);

    const float4* gp = (const float4*)g;
    const float4* bp = (const float4*)b;
    float4 g0 = gp[lane], g1 = gp[lane + 32];
    float4 b0 = bp[lane], b1 = bp[lane + 32];

    half2 h0a = __floats2half2_rn((v0.x - mean) * inv * g0.x + b0.x,
                                  (v0.y - mean) * inv * g0.y + b0.y);
    half2 h0b = __floats2half2_rn((v0.z - mean) * inv * g0.z + b0.z,
                                  (v0.w - mean) * inv * g0.w + b0.w);
    half2 h1a = __floats2half2_rn((v1.x - mean) * inv * g1.x + b1.x,
                                  (v1.y - mean) * inv * g1.y + b1.y);
    half2 h1b = __floats2half2_rn((v1.z - mean) * inv * g1.z + b1.z,
                                  (v1.w - mean) * inv * g1.w + b1.w);

    half2* op = (half2*)(out + (size_t)row * C_);
    op[lane * 2 + 0]  = h0a;
    op[lane * 2 + 1]  = h0b;
    op[lane * 2 + 64] = h1a;
    op[lane * 2 + 65] = h1b;
}

// ---------------------------------------------------------------------------
// fp16 mma.sync GEMM (m16n8k16): cp.async pipeline + ldmatrix fragments.
// (unchanged from R12 winner)
// EPI: 0 = plain fp32, 1 = +bias+relu fp16, 2 = +bias+residual fp32,
//      3 = plain fp16
// ---------------------------------------------------------------------------
#define GA_U32 (128 * 32)
#define GB_U32 (256 * 32)
#define GEMM_SMEM_BYTES (2 * (GA_U32 + GB_U32) * 4)   // 98304

template <int EPI>
__global__ __launch_bounds__(256, 1) void gemm_mma(
    const __half* __restrict__ A, const __half* __restrict__ Bt,
    void* __restrict__ Cm, const float* __restrict__ bias,
    const float* __restrict__ res, int M, int N, int K) {
    extern __shared__ uint32_t dynsm[];
    uint32_t* const Abuf[2] = { dynsm, dynsm + GA_U32 };
    uint32_t* const Bbuf[2] = { dynsm + 2 * GA_U32, dynsm + 2 * GA_U32 + GB_U32 };

    const int tid  = threadIdx.x;
    const int wid  = tid >> 5;
    const int lane = tid & 31;
    const int wm   = (wid & 1) * 64;
    const int wn   = (wid >> 1) * 64;
    const int gq   = lane >> 2;
    const int tq   = lane & 3;
    const int grp  = lane >> 3;
    const int ro   = lane & 7;
    const int brow = blockIdx.y * 128;
    const int bcol = blockIdx.x * 256;

    float acc[4][8][4];
#pragma unroll
    for (int i = 0; i < 4; i++)
#pragma unroll
        for (int j = 0; j < 8; j++)
#pragma unroll
            for (int q = 0; q < 4; q++) acc[i][j][q] = 0.0f;

    const __half* Ag = A + (size_t)brow * K;
    const __half* Bg = Bt + (size_t)bcol * K;
    const int KC = K >> 6;

    const int cr = tid >> 3;
    const int cc = (tid & 7) * 4;

    auto issue = [&](int kc, int s) {
        const __half* Agn = Ag + kc * 64 + cc * 2;
        const __half* Bgn = Bg + kc * 64 + cc * 2;
        uint32_t* As = Abuf[s];
        uint32_t* Bs = Bbuf[s];
#pragma unroll
        for (int i = 0; i < 4; i++) {
            int r = cr + i * 32;
            cp_async16(&As[r * 32 + swz(r, cc)], Agn + (size_t)r * K);
        }
#pragma unroll
        for (int i = 0; i < 8; i++) {
            int r = cr + i * 32;
            cp_async16(&Bs[r * 32 + swz(r, cc)], Bgn + (size_t)r * K);
        }
    };

    issue(0, 0); CP_COMMIT();
    if (KC > 1) issue(1, 1);
    CP_COMMIT();

    const int arow_lo = ro + (grp & 1) * 8;
    const int acol_off = (grp >> 1) * 4;
    const int brow_lo = ro + (grp >> 1) * 8;
    const int bcol_off = (grp & 1) * 4;

    for (int kc = 0; kc < KC; kc++) {
        CP_WAIT1();
        __syncthreads();

        const uint32_t Ab = (uint32_t)__cvta_generic_to_shared(Abuf[kc & 1]);
        const uint32_t Bb = (uint32_t)__cvta_generic_to_shared(Bbuf[kc & 1]);

#pragma unroll
        for (int ks = 0; ks < 4; ks++) {
            uint32_t afr[4][4];
#pragma unroll
            for (int mt = 0; mt < 4; mt++) {
                int row = wm + mt * 16 + arow_lo;
                uint32_t a = Ab + ((row * 32 + swz(row, ks * 8 + acol_off)) << 2);
                ldsm_x4(afr[mt], a);
            }
#pragma unroll
            for (int nb = 0; nb < 4; nb++) {
                int row = wn + nb * 16 + brow_lo;
                uint32_t a = Bb + ((row * 32 + swz(row, ks * 8 + bcol_off)) << 2);
                uint32_t kb[4];
                ldsm_x4(kb, a);
#pragma unroll
                for (int mt = 0; mt < 4; mt++) {
                    mma_f16v(acc[mt][2 * nb    ], afr[mt], kb[0], kb[1],
                             acc[mt][2 * nb    ]);
                    mma_f16v(acc[mt][2 * nb + 1], afr[mt], kb[2], kb[3],
                             acc[mt][2 * nb + 1]);
                }
            }
        }
        __syncthreads();
        if (kc + 2 < KC) issue(kc + 2, kc & 1);
        CP_COMMIT();
    }

#pragma unroll
    for (int mt = 0; mt < 4; mt++) {
        int row0 = brow + wm + mt * 16 + gq;
#pragma unroll
        for (int half_ = 0; half_ < 2; half_++) {
            int row = row0 + half_ * 8;
#pragma unroll
            for (int nt = 0; nt < 8; nt++) {
                int col = bcol + wn + nt * 8 + tq * 2;
                float vx = acc[mt][nt][half_ * 2 + 0];
                float vy = acc[mt][nt][half_ * 2 + 1];
                if (EPI == 1 || EPI == 2) {
                    vx += bias[col + 0];
                    vy += bias[col + 1];
                }
                if (EPI == 1) {
                    __half* outr = (__half*)Cm + (size_t)row * N;
                    *(half2*)(outr + col) =
                        __floats2half2_rn(fmaxf(vx, 0.0f), fmaxf(vy, 0.0f));
                } else if (EPI == 3) {
                    __half* outr = (__half*)Cm + (size_t)row * N;
                    *(half2*)(outr + col) = __floats2half2_rn(vx, vy);
                } else {
                    float* outr = (float*)Cm + (size_t)row * N;
                    if (EPI == 2) {
                        float2 rr = *(const float2*)(res + (size_t)row * N + col);
                        vx += rr.x;
                        vy += rr.y;
                    }
                    *(float2*)(outr + col) = make_float2(vx, vy);
                }
            }
        }
    }
}

// ---------------------------------------------------------------------------
// fp16 flash attention: ldmatrix + cp.async, P in registers,
// exp2-domain softmax (q pre-scaled by log2e), row-sum l via ones-B mma.
// ---------------------------------------------------------------------------
#define QST 20     // row stride in uint32
#define ONE2 0x3C003C00u   // half2(1.0, 1.0)

__global__ __launch_bounds__(128) void attn_tc_kernel(
    const __half* __restrict__ qkv, __half* __restrict__ att) {
    __shared__ uint32_t smQ[64 * QST];
    __shared__ uint32_t smK[2][64 * QST];
    __shared__ uint32_t smV[2][64 * QST];

    const int bh = blockIdx.x;
    const int b  = bh >> 3;
    const int h  = bh & 7;
    const int qt = blockIdx.y;
    const int tid  = threadIdx.x;
    const int wid  = tid >> 5;
    const int lane = tid & 31;
    const int gq   = lane >> 2;
    const int tq   = lane & 3;
    const int grp  = lane >> 3;
    const int ro   = lane & 7;
    const size_t tokbase = (size_t)b * T_;
    const int qrow0 = qt * 64;
    const int m0 = wid * 16;
    const int ntiles = qt + 1;

    auto issue = [&](int t, int s) {
#pragma unroll
        for (int i = 0; i < 2; i++) {
            int e = tid + i * 128;
            int r = e >> 2, c16 = e & 3;
            const __half* kg = qkv + (tokbase + t * 64 + r) * QKV_N + C_ + h * D_ + c16 * 8;
            cp_async16(&smK[s][r * QST + c16 * 4], kg);
            cp_async16(&smV[s][r * QST + c16 * 4], kg + C_);
        }
    };

    issue(0, 0); CP_COMMIT();
    if (ntiles > 1) issue(1, 1);
    CP_COMMIT();

#pragma unroll
    for (int i = 0; i < 2; i++) {
        int e = tid + i * 128;
        int r = e >> 2, c16 = e & 3;
        uint4 v = *(const uint4*)(qkv + (tokbase + qrow0 + r) * QKV_N + h * D_ + c16 * 8);
        *(uint4*)&smQ[r * QST + c16 * 4] = v;
    }
    __syncthreads();

    const uint32_t smQb = (uint32_t)__cvta_generic_to_shared(smQ);
    uint32_t qf[2][4];
#pragma unroll
    for (int ks = 0; ks < 2; ks++) {
        uint32_t a = smQb +
            (((m0 + ro + (grp & 1) * 8) * QST + ks * 8 + (grp >> 1) * 4) << 2);
        ldsm_x4(qf[ks], a);
    }

    const int r0 = qrow0 + m0 + gq;
    const int r1 = r0 + 8;

    float mrow0 = -1e30f, mrow1 = -1e30f;
    float l0 = 0.0f, l1 = 0.0f;
    float o[4][4];
#pragma unroll
    for (int i = 0; i < 4; i++)
#pragma unroll
        for (int j = 0; j < 4; j++) o[i][j] = 0.0f;

    for (int t = 0; t < ntiles; t++) {
        CP_WAIT1();
        __syncthreads();
        const int s = t & 1;
        const uint32_t Kb = (uint32_t)__cvta_generic_to_shared(smK[s]);
        const uint32_t Vb = (uint32_t)__cvta_generic_to_shared(smV[s]);

        // --- S = Q @ K^T (scores in log2 domain) ---
        float S[8][4];
#pragma unroll
        for (int nt = 0; nt < 8; nt++)
            S[nt][0] = S[nt][1] = S[nt][2] = S[nt][3] = 0.0f;
#pragma unroll
        for (int ks = 0; ks < 2; ks++) {
#pragma unroll
            for (int nb = 0; nb < 4; nb++) {
                uint32_t kb[4];
                uint32_t a = Kb +
                    (((nb * 16 + ro + (grp >> 1) * 8) * QST + ks * 8 + (grp & 1) * 4) << 2);
                ldsm_x4(kb, a);
                mma_f16v(S[2 * nb    ], qf[ks], kb[0], kb[1], S[2 * nb    ]);
                mma_f16v(S[2 * nb + 1], qf[ks], kb[2], kb[3], S[2 * nb + 1]);
            }
        }

        // --- causal mask (diagonal tile only) ---
        if (t == qt) {
#pragma unroll
            for (int nt = 0; nt < 8; nt++) {
                int col = qrow0 + nt * 8 + 2 * tq;
                if (col     > r0) S[nt][0] = -1e30f;
                if (col + 1 > r0) S[nt][1] = -1e30f;
                if (col     > r1) S[nt][2] = -1e30f;
                if (col + 1 > r1) S[nt][3] = -1e30f;
            }
        }

        // --- row max ---
        float mx0 = -1e30f, mx1 = -1e30f;
#pragma unroll
        for (int nt = 0; nt < 8; nt++) {
            mx0 = fmaxf(mx0, fmaxf(S[nt][0], S[nt][1]));
            mx1 = fmaxf(mx1, fmaxf(S[nt][2], S[nt][3]));
        }
        mx0 = fmaxf(mx0, __shfl_xor_sync(0xffffffffu, mx0, 1));
        mx0 = fmaxf(mx0, __shfl_xor_sync(0xffffffffu, mx0, 2));
        mx1 = fmaxf(mx1, __shfl_xor_sync(0xffffffffu, mx1, 1));
        mx1 = fmaxf(mx1, __shfl_xor_sync(0xffffffffu, mx1, 2));

        float mn0 = fmaxf(mrow0, mx0);
        float mn1 = fmaxf(mrow1, mx1);
        float a0 = exp2f(mrow0 - mn0);
        float a1 = exp2f(mrow1 - mn1);
        mrow0 = mn0;
        mrow1 = mn1;

        // --- P = exp2(S - m), packed straight into A-fragments ---
        uint32_t pf[4][4];
#pragma unroll
        for (int kp = 0; kp < 4; kp++) {
            pf[kp][0] = f2h2(exp2f(S[2 * kp    ][0] - mn0), exp2f(S[2 * kp    ][1] - mn0));
            pf[kp][1] = f2h2(exp2f(S[2 * kp    ][2] - mn1), exp2f(S[2 * kp    ][3] - mn1));
            pf[kp][2] = f2h2(exp2f(S[2 * kp + 1][0] - mn0), exp2f(S[2 * kp + 1][1] - mn0));
            pf[kp][3] = f2h2(exp2f(S[2 * kp + 1][2] - mn1), exp2f(S[2 * kp + 1][3] - mn1));
        }

        // --- row-sum l via ones-B mma (fully reduced, no shuffles) ---
        float dl[4] = {0.0f, 0.0f, 0.0f, 0.0f};
#pragma unroll
        for (int kp = 0; kp < 4; kp++)
            mma_f16v(dl, pf[kp], ONE2, ONE2, dl);
        l0 = l0 * a0 + dl[0];
        l1 = l1 * a1 + dl[2];

        // --- rescale O ---
#pragma unroll
        for (int d4 = 0; d4 < 4; d4++) {
            o[d4][0] *= a0;
            o[d4][1] *= a0;
            o[d4][2] *= a1;
            o[d4][3] *= a1;
        }

        // --- O += P @ V ---
#pragma unroll
        for (int j = 0; j < 2; j++) {
#pragma unroll
            for (int kp = 0; kp < 4; kp++) {
                uint32_t vb[4];
                uint32_t a = Vb +
                    (((kp * 16 + ro + (grp & 1) * 8) * QST + (j * 2 + (grp >> 1)) * 4) << 2);
                ldsm_x4_t(vb, a);
                mma_f16v(o[2 * j    ], pf[kp], vb[0], vb[1], o[2 * j    ]);
                mma_f16v(o[2 * j + 1], pf[kp], vb[2], vb[3], o[2 * j + 1]);
            }
        }
        __syncthreads();
        if (t + 2 < ntiles) issue(t + 2, s);
        CP_COMMIT();
    }

    float inv0 = 1.0f / l0;
    float inv1 = 1.0f / l1;
#pragma unroll
    for (int d4 = 0; d4 < 4; d4++) {
        int col = h * D_ + d4 * 8 + 2 * tq;
        *(half2*)(att + (tokbase + r0) * C_ + col) =
            __floats2half2_rn(o[d4][0] * inv0, o[d4][1] * inv0);
        *(half2*)(att + (tokbase + r1) * C_ + col) =
            __floats2half2_rn(o[d4][2] * inv1, o[d4][3] * inv1);
    }
}

// ---------------------------------------------------------------------------
// Launch
// ---------------------------------------------------------------------------
extern "C" void kernel_launch(void* const* d_in, const int* in_sizes, int n_in,
                              void* d_out, int out_size) {
    const float* x      = (const float*)d_in[0];
    const float* wq     = (const float*)d_in[1];
    const float* wk     = (const float*)d_in[2];
    const float* wv     = (const float*)d_in[3];
    const float* w_proj = (const float*)d_in[4];
    const float* b_proj = (const float*)d_in[5];
    const float* w1     = (const float*)d_in[6];
    const float* b1     = (const float*)d_in[7];
    const float* w2     = (const float*)d_in[8];
    const float* b2     = (const float*)d_in[9];
    const float* ln1_g  = (const float*)d_in[10];
    const float* ln1_b  = (const float*)d_in[11];
    const float* ln2_g  = (const float*)d_in[12];
    const float* ln2_b  = (const float*)d_in[13];
    float* out = (float*)d_out;

    __half *p_h, *p_qkv, *p_att, *p_h2, *p_ffn;
    __half *p_wqkvT, *p_wprojT, *p_w1T, *p_w2T;
    float *p_xmid;
    cudaGetSymbolAddress((void**)&p_h,      g_h);
    cudaGetSymbolAddress((void**)&p_qkv,    g_qkv);
    cudaGetSymbolAddress((void**)&p_att,    g_att);
    cudaGetSymbolAddress((void**)&p_xmid,   g_xmid);
    cudaGetSymbolAddress((void**)&p_h2,     g_h2);
    cudaGetSymbolAddress((void**)&p_ffn,    g_ffn);
    cudaGetSymbolAddress((void**)&p_wqkvT,  g_wqkvT);
    cudaGetSymbolAddress((void**)&p_wprojT, g_wprojT);
    cudaGetSymbolAddress((void**)&p_w1T,    g_w1T);
    cudaGetSymbolAddress((void**)&p_w2T,    g_w2T);

    cudaFuncSetAttribute(gemm_mma<1>, cudaFuncAttributeMaxDynamicSharedMemorySize, GEMM_SMEM_BYTES);
    cudaFuncSetAttribute(gemm_mma<2>, cudaFuncAttributeMaxDynamicSharedMemorySize, GEMM_SMEM_BYTES);
    cudaFuncSetAttribute(gemm_mma<3>, cudaFuncAttributeMaxDynamicSharedMemorySize, GEMM_SMEM_BYTES);

    // weight prep
    prep_weights_kernel<<<(PREP_TOTAL + 255) / 256, 256>>>(
        wq, wk, wv, w_proj, w1, w2, p_wqkvT, p_wprojT, p_w1T, p_w2T);

    // 1. h = ln1(x)                       (fp16)
    layernorm_kernel<<<M_TOK / 8, 256>>>(x, ln1_g, ln1_b, p_h);

    // 2. qkv = h @ Wqkv                   (fp16; q pre-scaled *log2e)
    gemm_mma<3><<<dim3(QKV_N / 256, M_TOK / 128), 256, GEMM_SMEM_BYTES>>>(
        p_h, p_wqkvT, p_qkv, nullptr, nullptr, M_TOK, QKV_N, C_);

    // 3. causal attention                 (fp16 in/out, exp2 softmax)
    attn_tc_kernel<<<dim3(B_ * H_, T_ / 64), 128>>>(p_qkv, p_att);

    // 4. xmid = x + att @ w_proj + b_proj (fp32)
    gemm_mma<2><<<dim3(C_ / 256, M_TOK / 128), 256, GEMM_SMEM_BYTES>>>(
        p_att, p_wprojT, p_xmid, b_proj, x, M_TOK, C_, C_);

    // 5. h2 = ln2(xmid)                   (fp16)
    layernorm_kernel<<<M_TOK / 8, 256>>>(p_xmid, ln2_g, ln2_b, p_h2);

    // 6. ffn = relu(h2 @ w1 + b1)         (fp16)
    gemm_mma<1><<<dim3(FF_ / 256, M_TOK / 128), 256, GEMM_SMEM_BYTES>>>(
        p_h2, p_w1T, p_ffn, b1, nullptr, M_TOK, FF_, C_);

    // 7. out = xmid + ffn @ w2 + b2       (fp32)
    gemm_mma<2><<<dim3(C_ / 256, M_TOK / 128), 256, GEMM_SMEM_BYTES>>>(
        p_ffn, p_w2T, out, b2, p_xmid, M_TOK, C_, FF_);
}